// round 14
// baseline (speedup 1.0000x reference)
#include <cuda_runtime.h>
#include <math.h>
#include <stdint.h>

#define BB 8
#define LL 4096
#define CIN 96
#define DI 192
#define KK 4
#define RR 6
#define NN 16
#define KRR 24
#define NCH 64
#define TT 64
#define CPROJ 38
#define KC 152   // KK*CPROJ

typedef unsigned long long ull;
__device__ __forceinline__ ull fma2(ull a, ull b, ull c) {
    ull d; asm("fma.rn.f32x2 %0, %1, %2, %3;" : "=l"(d) : "l"(a), "l"(b), "l"(c)); return d;
}
__device__ __forceinline__ ull mul2(ull a, ull b) {
    ull d; asm("mul.rn.f32x2 %0, %1, %2;" : "=l"(d) : "l"(a), "l"(b)); return d;
}
__device__ __forceinline__ ull bcast2(float x) {
    ull r; asm("mov.b64 %0, {%1, %1};" : "=l"(r) : "f"(x)); return r;
}
__device__ __forceinline__ float2 unpk(ull v) {
    float a, b; asm("mov.b64 {%0, %1}, %2;" : "=f"(a), "=f"(b) : "l"(v)); return make_float2(a, b);
}

// scratch (static device globals; no allocation)
__device__ float  d_z [BB*LL*DI];
__device__ float  d_xi[BB*LL*DI];
__device__ float  d_BC[BB*LL*KK*32];          // per (b,l,k): B[0..15], C[16..31]
__device__ float2 d_dtdk[BB*LL*KK*RR];        // (dt, decay)
__device__ float  d_ys[BB*LL*KK*RR*32];
__device__ float  d_P [BB*KRR*LL];            // cumulative within-chunk decay
__device__ float  d_h [BB*KRR*NCH*32*NN];     // chunk-end states (from A)
__device__ float  d_h0[BB*KRR*NCH*32*NN];     // chunk-start states (from B)

__device__ __forceinline__ int tau_idx(int l) { return ((l & 63) << 6) | (l >> 6); }
__device__ __forceinline__ int sigma_k(int k, int l) {
    int t = (k & 1) ? tau_idx(l) : l;
    return (k >= 2) ? (4095 - t) : t;
}
__device__ __forceinline__ uint32_t f2tf32(float v) {
    uint32_t o; asm("cvt.rna.tf32.f32 %0, %1;" : "=r"(o) : "f"(v)); return o;
}

// ---------- K1: z = x @ w_in (scalar float4, 16px x 2out)  [round-7 exact] ----------
__global__ __launch_bounds__(192) void k1_inproj(const float* __restrict__ x,
                                                 const float* __restrict__ w_in) {
    __shared__ __align__(16) float sx[32 * CIN];
    int pix0 = blockIdx.x * 32;
    int t = threadIdx.x;  // 192
    const float4* xg = reinterpret_cast<const float4*>(x + pix0 * CIN);
    float4* sx4s = reinterpret_cast<float4*>(sx);
    for (int i = t; i < 32 * CIN / 4; i += 192) sx4s[i] = xg[i];
    __syncthreads();
    const float4* sx4 = reinterpret_cast<const float4*>(sx);
    int row = t / 96;      // 0..1 -> pixels row*16 .. +15
    int col = t % 96;      // outputs 2col, 2col+1
    float a0[16], a1[16];
#pragma unroll
    for (int p = 0; p < 16; p++) { a0[p] = 0.f; a1[p] = 0.f; }
    for (int i4 = 0; i4 < CIN / 4; i4++) {
        float2 w0 = *reinterpret_cast<const float2*>(&w_in[(i4 * 4 + 0) * DI + 2 * col]);
        float2 w1 = *reinterpret_cast<const float2*>(&w_in[(i4 * 4 + 1) * DI + 2 * col]);
        float2 w2 = *reinterpret_cast<const float2*>(&w_in[(i4 * 4 + 2) * DI + 2 * col]);
        float2 w3 = *reinterpret_cast<const float2*>(&w_in[(i4 * 4 + 3) * DI + 2 * col]);
#pragma unroll
        for (int p = 0; p < 16; p++) {
            float4 xv = sx4[(row * 16 + p) * (CIN / 4) + i4];
            a0[p] = fmaf(xv.x, w0.x, a0[p]); a1[p] = fmaf(xv.x, w0.y, a1[p]);
            a0[p] = fmaf(xv.y, w1.x, a0[p]); a1[p] = fmaf(xv.y, w1.y, a1[p]);
            a0[p] = fmaf(xv.z, w2.x, a0[p]); a1[p] = fmaf(xv.z, w2.y, a1[p]);
            a0[p] = fmaf(xv.w, w3.x, a0[p]); a1[p] = fmaf(xv.w, w3.y, a1[p]);
        }
    }
#pragma unroll
    for (int p = 0; p < 16; p++) {
        float2 v = make_float2(a0[p], a1[p]);
        *reinterpret_cast<float2*>(&d_z[(pix0 + row * 16 + p) * DI + 2 * col]) = v;
    }
}

// ---------- K2: depthwise 3x3 conv + bias + silu [round-7 exact] ----------
__global__ void k2_conv(const float* __restrict__ wc, const float* __restrict__ bcv) {
    int c = threadIdx.x;               // 0..191
    int seg = blockIdx.x;              // 4096
    int b = seg >> 9;
    int h = (seg >> 3) & 63;
    int w0 = (seg & 7) << 3;
    float wreg[9];
#pragma unroll
    for (int i = 0; i < 9; i++) wreg[i] = wc[i * DI + c];
    float row[3][10];
#pragma unroll
    for (int dh = 0; dh < 3; dh++) {
        int hh = h + dh - 1;
        bool hok = (hh >= 0 && hh < 64);
#pragma unroll
        for (int dw = 0; dw < 10; dw++) {
            int ww = w0 + dw - 1;
            row[dh][dw] = (hok && ww >= 0 && ww < 64)
                ? d_z[(((b << 12) + (hh << 6) + ww)) * DI + c] : 0.f;
        }
    }
    float bias = bcv[c];
#pragma unroll
    for (int q = 0; q < 8; q++) {
        float acc = bias;
#pragma unroll
        for (int dh = 0; dh < 3; dh++)
#pragma unroll
            for (int dw = 0; dw < 3; dw++)
                acc = fmaf(row[dh][q + dw], wreg[dh * 3 + dw], acc);
        int pix = (b << 12) + (h << 6) + w0 + q;
        d_xi[pix * DI + c] = acc / (1.f + expf(-acc));
    }
}

// ---------- K3: projection GEMM via mma.sync tf32 [round-7 exact] ----------
#define SAK 196
#define SBK 196
#define SA_FLOATS (128 * SAK)
#define SB_FLOATS (152 * SBK)
#define K3_SMEM_BYTES ((SA_FLOATS + SB_FLOATS + 64) * 4)

__global__ __launch_bounds__(256) void k3_mma(const float* __restrict__ xpw,
                                              const float* __restrict__ Alogs,
                                              const float* __restrict__ dtb) {
    extern __shared__ __align__(16) uint32_t smem[];
    uint32_t* sA = smem;
    uint32_t* sB = smem + SA_FLOATS;
    float* sAk  = reinterpret_cast<float*>(smem + SA_FLOATS + SB_FLOATS);
    float* sdtb = sAk + KRR;

    int t = threadIdx.x;                 // 256
    int wid = t >> 5, lane = t & 31;
    int g = lane >> 2, tg = lane & 3;

    int pix0 = blockIdx.x * 128;
    int b = pix0 >> 12;
    int l0 = pix0 & 4095;

    if (t < KRR) { sAk[t] = -expf(Alogs[t]); sdtb[t] = dtb[t]; }

    {
        const float4* src = reinterpret_cast<const float4*>(d_xi + pix0 * DI);
        for (int idx = t; idx < 128 * 48; idx += 256) {
            int row = idx / 48, c4 = idx % 48;
            float4 v = src[idx];
            uint4 tv = make_uint4(f2tf32(v.x), f2tf32(v.y), f2tf32(v.z), f2tf32(v.w));
            *reinterpret_cast<uint4*>(&sA[row * SAK + c4 * 4]) = tv;
        }
    }
    {
        const float4* src = reinterpret_cast<const float4*>(xpw);
        for (int idx = t; idx < 152 * 48; idx += 256) {
            int n = idx / 48, c4 = idx % 48;
            float4 v = src[idx];
            uint4 tv = make_uint4(f2tf32(v.x), f2tf32(v.y), f2tf32(v.z), f2tf32(v.w));
            *reinterpret_cast<uint4*>(&sB[n * SBK + c4 * 4]) = tv;
        }
    }
    __syncthreads();

    int m0 = wid * 16;
    int row0 = m0 + g, row1 = m0 + g + 8;
    float cacc[19][4];
#pragma unroll
    for (int nt = 0; nt < 19; nt++)
#pragma unroll
        for (int j = 0; j < 4; j++) cacc[nt][j] = 0.f;

    const uint32_t* pa0 = &sA[row0 * SAK + tg];
    const uint32_t* pa1 = &sA[row1 * SAK + tg];
#pragma unroll 4
    for (int k0 = 0; k0 < 192; k0 += 8) {
        uint32_t a0 = pa0[k0], a2 = pa0[k0 + 4];
        uint32_t a1 = pa1[k0], a3 = pa1[k0 + 4];
        const uint32_t* pb = &sB[g * SBK + k0 + tg];
#pragma unroll
        for (int nt = 0; nt < 19; nt++) {
            uint32_t b0 = pb[nt * 8 * SBK];
            uint32_t b1 = pb[nt * 8 * SBK + 4];
            asm volatile(
                "mma.sync.aligned.m16n8k8.row.col.f32.tf32.tf32.f32 "
                "{%0,%1,%2,%3}, {%4,%5,%6,%7}, {%8,%9}, {%0,%1,%2,%3};"
                : "+f"(cacc[nt][0]), "+f"(cacc[nt][1]), "+f"(cacc[nt][2]), "+f"(cacc[nt][3])
                : "r"(a0), "r"(a1), "r"(a2), "r"(a3), "r"(b0), "r"(b1));
        }
    }

#pragma unroll
    for (int nt = 0; nt < 19; nt++) {
        int kc = nt * 8 + 2 * tg;
        int k = kc / CPROJ;
        int c = kc - k * CPROJ;
#pragma unroll
        for (int hh = 0; hh < 2; hh++) {
            int row = (hh == 0) ? row0 : row1;
            float v0 = cacc[nt][2 * hh + 0], v1 = cacc[nt][2 * hh + 1];
            int pos = sigma_k(k, l0 + row);
            if (c < RR) {
                float A0 = sAk[k * RR + c],     tb0 = sdtb[k * RR + c];
                float A1 = sAk[k * RR + c + 1], tb1 = sdtb[k * RR + c + 1];
                float x0 = v0 + tb0, x1 = v1 + tb1;
                float dt0 = (x0 > 20.f) ? x0 : log1pf(expf(x0));
                float dt1 = (x1 > 20.f) ? x1 : log1pf(expf(x1));
                float4 w = make_float4(dt0, expf(dt0 * A0), dt1, expf(dt1 * A1));
                *reinterpret_cast<float4*>(&d_dtdk[((b * LL + pos) * KK + k) * RR + c]) = w;
            } else {
                *reinterpret_cast<float2*>(&d_BC[((b * LL + pos) * KK + k) * 32 + (c - RR)]) =
                    make_float2(v0, v1);
            }
        }
    }
}

// ---------- K4A: staged u + f32x2 state pairs [round-11 exact] ----------
__global__ __launch_bounds__(192) void k4_scanA(const float* __restrict__ Ds) {
    __shared__ __align__(16) float4 sBC[TT * 8];   // 8KB
    __shared__ float2 sdt[TT * RR];                // 3KB
    __shared__ float  su[32 * DI];                 // 24KB
    int bx = blockIdx.x;                 // 2048 = b(8) * k(4) * chunk(64)
    int chunk = bx & 63, k = (bx >> 6) & 3, b = bx >> 8;
    int t = threadIdx.x;
    int warp = t >> 5, lane = t & 31;
    int l0 = chunk * TT;

    const float4* bc4 = reinterpret_cast<const float4*>(d_BC);
    int g4 = ((b * LL + l0) * KK + k) * 8;
    for (int j = t; j < TT * 8; j += 192) {
        int s = j >> 3, w = j & 7;
        sBC[j] = bc4[g4 + s * KK * 8 + w];
    }
    int gd = ((b * LL + l0) * KK + k) * RR;
    for (int j = t; j < TT * RR; j += 192) {
        int s = j / RR, r = j % RR;
        sdt[j] = d_dtdk[gd + s * KK * RR + r];
    }

    int ubase, ustride;
    if (k == 0)      { ubase = l0;        ustride = 1;   }
    else if (k == 1) { ubase = chunk;     ustride = 64;  }
    else if (k == 2) { ubase = 4095 - l0; ustride = -1;  }
    else             { ubase = 4095 - chunk; ustride = -64; }

    int r = warp;  // 0..5
    int sl = b * KRR + k * RR + r;
    float Dd = Ds[(k * RR + r) * 32 + lane];

    ull hp[8];
#pragma unroll
    for (int n = 0; n < 8; n++) hp[n] = 0ULL;
    float P = 1.f;
    int ysIdx = ((b * LL + l0) * KK + k) * 192 + r * 32 + lane;
    int pIdx  = sl * LL + l0;

    const float* ubp = d_xi + (long)(b * LL + ubase) * DI + t;
    long ustepL = (long)ustride * DI;
    const ulonglong2* sBC2 = reinterpret_cast<const ulonglong2*>(sBC);

#pragma unroll
    for (int half = 0; half < 2; half++) {
        __syncthreads();
        {
            const float* up = ubp + (long)(half * 32) * ustepL;
#pragma unroll 8
            for (int sl2 = 0; sl2 < 32; sl2++) {
                su[sl2 * DI + t] = *up;
                up += ustepL;
            }
        }
        __syncthreads();

#pragma unroll 2
        for (int s2 = 0; s2 < 32; s2++) {
            int s = half * 32 + s2;
            float u = su[s2 * DI + r * 32 + lane];
            float2 dd = sdt[s * RR + r];
            ulonglong2 b01 = sBC2[s * 8 + 0], b23 = sBC2[s * 8 + 1];
            ulonglong2 b45 = sBC2[s * 8 + 2], b67 = sBC2[s * 8 + 3];
            ulonglong2 c01 = sBC2[s * 8 + 4], c23 = sBC2[s * 8 + 5];
            ulonglong2 c45 = sBC2[s * 8 + 6], c67 = sBC2[s * 8 + 7];
            ull Bp[8] = {b01.x, b01.y, b23.x, b23.y, b45.x, b45.y, b67.x, b67.y};
            ull Cp[8] = {c01.x, c01.y, c23.x, c23.y, c45.x, c45.y, c67.x, c67.y};
            ull dkb = bcast2(dd.y);
            ull xub = bcast2(dd.x * u);
            ull yp = 0ULL;
#pragma unroll
            for (int n = 0; n < 8; n++) {
                hp[n] = fma2(dkb, hp[n], mul2(xub, Bp[n]));
                yp = fma2(hp[n], Cp[n], yp);
            }
            P *= dd.y;
            float2 yy = unpk(yp);
            d_ys[ysIdx] = fmaf(u, Dd, yy.x + yy.y);
            if (lane == 0) d_P[pIdx] = P;
            ysIdx += KK * 192; pIdx += 1;
        }
    }
    ulonglong2* hout = reinterpret_cast<ulonglong2*>(d_h + ((sl * NCH + chunk) * 32 + lane) * NN);
    hout[0] = make_ulonglong2(hp[0], hp[1]);
    hout[1] = make_ulonglong2(hp[2], hp[3]);
    hout[2] = make_ulonglong2(hp[4], hp[5]);
    hout[3] = make_ulonglong2(hp[6], hp[7]);
}

// ---------- K4B: carry across chunks; group-of-4 double-buffered pipeline ----------
__global__ __launch_bounds__(256, 1) void k4_scanB() {
    int wid = (blockIdx.x * blockDim.x + threadIdx.x) >> 5;  // 0..191
    int lane = threadIdx.x & 31;
    float h0[NN];
#pragma unroll
    for (int n = 0; n < NN; n++) h0[n] = 0.f;

    // float4 view: state for (wid, chunk c, lane) at d_h + ((wid*NCH+c)*32+lane)*NN
    float4 bufA[4][4], bufB[4][4];
    float  dA[4], dB[4];

    // preload group 0 (chunks 0..3)
#pragma unroll
    for (int j = 0; j < 4; j++) {
        const float4* src = reinterpret_cast<const float4*>(
            d_h + ((wid * NCH + j) * 32 + lane) * NN);
        bufA[j][0] = src[0]; bufA[j][1] = src[1]; bufA[j][2] = src[2]; bufA[j][3] = src[3];
        dA[j] = d_P[wid * LL + j * TT + TT - 1];
    }

    for (int g = 0; g < 16; g += 2) {
        // prefetch group g+1 into bufB
#pragma unroll
        for (int j = 0; j < 4; j++) {
            int c = (g + 1) * 4 + j;
            const float4* src = reinterpret_cast<const float4*>(
                d_h + ((wid * NCH + c) * 32 + lane) * NN);
            bufB[j][0] = src[0]; bufB[j][1] = src[1]; bufB[j][2] = src[2]; bufB[j][3] = src[3];
            dB[j] = d_P[wid * LL + c * TT + TT - 1];
        }
        // process group g from bufA
#pragma unroll
        for (int j = 0; j < 4; j++) {
            int c = g * 4 + j;
            float4* dst = reinterpret_cast<float4*>(
                d_h0 + ((wid * NCH + c) * 32 + lane) * NN);
            dst[0] = make_float4(h0[0], h0[1], h0[2], h0[3]);
            dst[1] = make_float4(h0[4], h0[5], h0[6], h0[7]);
            dst[2] = make_float4(h0[8], h0[9], h0[10], h0[11]);
            dst[3] = make_float4(h0[12], h0[13], h0[14], h0[15]);
            float Dc = dA[j];
            const float4* aq = bufA[j];
            float av[NN] = {aq[0].x,aq[0].y,aq[0].z,aq[0].w, aq[1].x,aq[1].y,aq[1].z,aq[1].w,
                            aq[2].x,aq[2].y,aq[2].z,aq[2].w, aq[3].x,aq[3].y,aq[3].z,aq[3].w};
#pragma unroll
            for (int n = 0; n < NN; n++) h0[n] = fmaf(Dc, h0[n], av[n]);
        }
        // prefetch group g+2 into bufA
        if (g + 2 < 16) {
#pragma unroll
            for (int j = 0; j < 4; j++) {
                int c = (g + 2) * 4 + j;
                const float4* src = reinterpret_cast<const float4*>(
                    d_h + ((wid * NCH + c) * 32 + lane) * NN);
                bufA[j][0] = src[0]; bufA[j][1] = src[1]; bufA[j][2] = src[2]; bufA[j][3] = src[3];
                dA[j] = d_P[wid * LL + c * TT + TT - 1];
            }
        }
        // process group g+1 from bufB
#pragma unroll
        for (int j = 0; j < 4; j++) {
            int c = (g + 1) * 4 + j;
            float4* dst = reinterpret_cast<float4*>(
                d_h0 + ((wid * NCH + c) * 32 + lane) * NN);
            dst[0] = make_float4(h0[0], h0[1], h0[2], h0[3]);
            dst[1] = make_float4(h0[4], h0[5], h0[6], h0[7]);
            dst[2] = make_float4(h0[8], h0[9], h0[10], h0[11]);
            dst[3] = make_float4(h0[12], h0[13], h0[14], h0[15]);
            float Dc = dB[j];
            const float4* aq = bufB[j];
            float av[NN] = {aq[0].x,aq[0].y,aq[0].z,aq[0].w, aq[1].x,aq[1].y,aq[1].z,aq[1].w,
                            aq[2].x,aq[2].y,aq[2].z,aq[2].w, aq[3].x,aq[3].y,aq[3].z,aq[3].w};
#pragma unroll
            for (int n = 0; n < NN; n++) h0[n] = fmaf(Dc, h0[n], av[n]);
        }
    }
}

// ---------- K4C: fixup ys += P_l * (h0 . C_l); f32x2 [round-11 exact] ----------
__global__ __launch_bounds__(192) void k4_scanC() {
    __shared__ __align__(16) float4 sC[TT * 4];  // 4KB
    __shared__ float sP[RR * TT];                // 1.5KB
    int bx = blockIdx.x;
    int chunk = bx & 63, k = (bx >> 6) & 3, b = bx >> 8;
    int t = threadIdx.x;
    int warp = t >> 5, lane = t & 31;
    int l0 = chunk * TT;

    const float4* bc4 = reinterpret_cast<const float4*>(d_BC);
    int g4 = ((b * LL + l0) * KK + k) * 8;
    for (int j = t; j < TT * 4; j += 192) {
        int s = j >> 2, w = j & 3;
        sC[j] = bc4[g4 + s * KK * 8 + 4 + w];
    }
    for (int j = t; j < RR * TT; j += 192) {
        int r = j / TT, s = j % TT;
        sP[j] = d_P[(b * KRR + k * RR + r) * LL + l0 + s];
    }
    __syncthreads();

    int r = warp;
    int sl = b * KRR + k * RR + r;
    const ulonglong2* hp2 = reinterpret_cast<const ulonglong2*>(
        d_h0 + ((sl * NCH + chunk) * 32 + lane) * NN);
    ulonglong2 h01 = hp2[0], h23 = hp2[1], h45 = hp2[2], h67 = hp2[3];
    ull h0p[8] = {h01.x, h01.y, h23.x, h23.y, h45.x, h45.y, h67.x, h67.y};

    const ulonglong2* sC2 = reinterpret_cast<const ulonglong2*>(sC);
    int ysIdx = ((b * LL + l0) * KK + k) * 192 + r * 32 + lane;
#pragma unroll 2
    for (int s = 0; s < TT; s++) {
        ulonglong2 c01 = sC2[s * 4 + 0], c23 = sC2[s * 4 + 1];
        ulonglong2 c45 = sC2[s * 4 + 2], c67 = sC2[s * 4 + 3];
        ull Cp[8] = {c01.x, c01.y, c23.x, c23.y, c45.x, c45.y, c67.x, c67.y};
        ull corrp = 0ULL;
#pragma unroll
        for (int n = 0; n < 8; n++) corrp = fma2(h0p[n], Cp[n], corrp);
        float2 cc = unpk(corrp);
        d_ys[ysIdx] = fmaf(sP[r * TT + s], cc.x + cc.y, d_ys[ysIdx]);
        ysIdx += KK * 192;
    }
}

// ---------- K5: cross-merge + LayerNorm + out-proj [round-7 exact] ----------
__global__ __launch_bounds__(192) void k5_out(const float* __restrict__ lng,
                                              const float* __restrict__ lnb,
                                              const float* __restrict__ wout,
                                              float* __restrict__ out) {
    __shared__ __align__(16) float sy[32 * DI];   // 24KB
    __shared__ float smu[32], srs[32];
    int t = threadIdx.x;  // 192
    int pb = blockIdx.x * 32;    // 32 | 4096: never crosses batch
    int b = pb >> 12;
    int lbase = pb & 4095;

    for (int p = 0; p < 32; p++) {
        int l = lbase + p;
        float v = 0.f;
#pragma unroll
        for (int k = 0; k < KK; k++) {
            int pos = sigma_k(k, l);
            v += d_ys[((b * LL + pos) * KK + k) * 192 + t];
        }
        sy[p * DI + t] = v;
    }
    __syncthreads();

    int warp = t >> 5, lane = t & 31;
    for (int p = warp; p < 32; p += 6) {
        float s1 = 0.f, s2 = 0.f;
#pragma unroll
        for (int j = 0; j < 6; j++) {
            float v = sy[p * DI + lane + j * 32];
            s1 += v; s2 = fmaf(v, v, s2);
        }
#pragma unroll
        for (int o = 16; o > 0; o >>= 1) {
            s1 += __shfl_down_sync(0xffffffffu, s1, o);
            s2 += __shfl_down_sync(0xffffffffu, s2, o);
        }
        if (lane == 0) {
            float mu = s1 * (1.f / DI);
            float var = s2 * (1.f / DI) - mu * mu;
            smu[p] = mu;
            srs[p] = rsqrtf(var + 1e-5f);
        }
    }
    __syncthreads();

    float g = lng[t], be = lnb[t];
    for (int p = 0; p < 32; p++)
        sy[p * DI + t] = (sy[p * DI + t] - smu[p]) * srs[p] * g + be;
    __syncthreads();

    const float4* sy4 = reinterpret_cast<const float4*>(sy);
    int row = t / 48;     // 0..3 -> pixels row*8 .. +7
    int col = t % 48;     // outputs 2col, 2col+1
    float a0[8], a1[8];
#pragma unroll
    for (int q = 0; q < 8; q++) { a0[q] = 0.f; a1[q] = 0.f; }
    for (int c4 = 0; c4 < DI / 4; c4++) {
        float2 w0 = *reinterpret_cast<const float2*>(&wout[(c4 * 4 + 0) * 96 + 2 * col]);
        float2 w1 = *reinterpret_cast<const float2*>(&wout[(c4 * 4 + 1) * 96 + 2 * col]);
        float2 w2 = *reinterpret_cast<const float2*>(&wout[(c4 * 4 + 2) * 96 + 2 * col]);
        float2 w3 = *reinterpret_cast<const float2*>(&wout[(c4 * 4 + 3) * 96 + 2 * col]);
#pragma unroll
        for (int q = 0; q < 8; q++) {
            float4 sv = sy4[(row * 8 + q) * (DI / 4) + c4];
            a0[q] = fmaf(sv.x, w0.x, a0[q]); a1[q] = fmaf(sv.x, w0.y, a1[q]);
            a0[q] = fmaf(sv.y, w1.x, a0[q]); a1[q] = fmaf(sv.y, w1.y, a1[q]);
            a0[q] = fmaf(sv.z, w2.x, a0[q]); a1[q] = fmaf(sv.z, w2.y, a1[q]);
            a0[q] = fmaf(sv.w, w3.x, a0[q]); a1[q] = fmaf(sv.w, w3.y, a1[q]);
        }
    }
#pragma unroll
    for (int q = 0; q < 8; q++) {
        float2 v = make_float2(a0[q], a1[q]);
        *reinterpret_cast<float2*>(&out[(pb + row * 8 + q) * 96 + 2 * col]) = v;
    }
}

extern "C" void kernel_launch(void* const* d_in, const int* in_sizes, int n_in,
                              void* d_out, int out_size) {
    const float* x    = (const float*)d_in[0];
    const float* w_in = (const float*)d_in[1];
    const float* wconv= (const float*)d_in[2];
    const float* bconv= (const float*)d_in[3];
    const float* xpw  = (const float*)d_in[4];
    const float* Alog = (const float*)d_in[5];
    const float* Ds   = (const float*)d_in[6];
    const float* dtb  = (const float*)d_in[7];
    const float* lng  = (const float*)d_in[8];
    const float* lnb  = (const float*)d_in[9];
    const float* wout = (const float*)d_in[10];
    float* out = (float*)d_out;

    cudaFuncSetAttribute(k3_mma, cudaFuncAttributeMaxDynamicSharedMemorySize, K3_SMEM_BYTES);

    k1_inproj<<<BB * LL / 32, 192>>>(x, w_in);
    k2_conv<<<BB * LL / 8, DI>>>(wconv, bconv);
    k3_mma<<<BB * LL / 128, 256, K3_SMEM_BYTES>>>(xpw, Alog, dtb);
    k4_scanA<<<BB * KK * NCH, 192>>>(Ds);
    k4_scanB<<<24, 256>>>();
    k4_scanC<<<BB * KK * NCH, 192>>>();
    k5_out<<<BB * LL / 32, 192>>>(lng, lnb, wout, out);
}

// round 15
// speedup vs baseline: 1.0436x; 1.0436x over previous
#include <cuda_runtime.h>
#include <math.h>
#include <stdint.h>

#define BB 8
#define LL 4096
#define CIN 96
#define DI 192
#define KK 4
#define RR 6
#define NN 16
#define KRR 24
#define NCH 64
#define TT 64
#define CPROJ 38
#define KC 152   // KK*CPROJ

typedef unsigned long long ull;
__device__ __forceinline__ ull fma2(ull a, ull b, ull c) {
    ull d; asm("fma.rn.f32x2 %0, %1, %2, %3;" : "=l"(d) : "l"(a), "l"(b), "l"(c)); return d;
}
__device__ __forceinline__ ull mul2(ull a, ull b) {
    ull d; asm("mul.rn.f32x2 %0, %1, %2;" : "=l"(d) : "l"(a), "l"(b)); return d;
}
__device__ __forceinline__ ull bcast2(float x) {
    ull r; asm("mov.b64 %0, {%1, %1};" : "=l"(r) : "f"(x)); return r;
}
__device__ __forceinline__ float2 unpk(ull v) {
    float a, b; asm("mov.b64 {%0, %1}, %2;" : "=f"(a), "=f"(b) : "l"(v)); return make_float2(a, b);
}

// scratch (static device globals; no allocation)
__device__ float  d_z [BB*LL*DI];
__device__ float  d_xi[BB*LL*DI];
__device__ float  d_BC[BB*LL*KK*32];          // per (b,l,k): B[0..15], C[16..31]
__device__ float2 d_dtdk[BB*LL*KK*RR];        // (dt, decay)
__device__ float  d_ys[BB*LL*KK*RR*32];
__device__ float  d_P [BB*KRR*LL];            // cumulative within-chunk decay
__device__ float  d_h [BB*KRR*NCH*32*NN];     // chunk-end states (from A)
__device__ float  d_h0[BB*KRR*NCH*32*NN];     // chunk-start states (from B)

__device__ __forceinline__ int tau_idx(int l) { return ((l & 63) << 6) | (l >> 6); }
__device__ __forceinline__ int sigma_k(int k, int l) {
    int t = (k & 1) ? tau_idx(l) : l;
    return (k >= 2) ? (4095 - t) : t;
}
__device__ __forceinline__ uint32_t f2tf32(float v) {
    uint32_t o; asm("cvt.rna.tf32.f32 %0, %1;" : "=r"(o) : "f"(v)); return o;
}

// ---------- K1: z = x @ w_in (scalar float4, 16px x 2out) ----------
__global__ __launch_bounds__(192) void k1_inproj(const float* __restrict__ x,
                                                 const float* __restrict__ w_in) {
    __shared__ __align__(16) float sx[32 * CIN];
    int pix0 = blockIdx.x * 32;
    int t = threadIdx.x;  // 192
    const float4* xg = reinterpret_cast<const float4*>(x + pix0 * CIN);
    float4* sx4s = reinterpret_cast<float4*>(sx);
    for (int i = t; i < 32 * CIN / 4; i += 192) sx4s[i] = xg[i];
    __syncthreads();
    const float4* sx4 = reinterpret_cast<const float4*>(sx);
    int row = t / 96;      // 0..1 -> pixels row*16 .. +15
    int col = t % 96;      // outputs 2col, 2col+1
    float a0[16], a1[16];
#pragma unroll
    for (int p = 0; p < 16; p++) { a0[p] = 0.f; a1[p] = 0.f; }
    for (int i4 = 0; i4 < CIN / 4; i4++) {
        float2 w0 = *reinterpret_cast<const float2*>(&w_in[(i4 * 4 + 0) * DI + 2 * col]);
        float2 w1 = *reinterpret_cast<const float2*>(&w_in[(i4 * 4 + 1) * DI + 2 * col]);
        float2 w2 = *reinterpret_cast<const float2*>(&w_in[(i4 * 4 + 2) * DI + 2 * col]);
        float2 w3 = *reinterpret_cast<const float2*>(&w_in[(i4 * 4 + 3) * DI + 2 * col]);
#pragma unroll
        for (int p = 0; p < 16; p++) {
            float4 xv = sx4[(row * 16 + p) * (CIN / 4) + i4];
            a0[p] = fmaf(xv.x, w0.x, a0[p]); a1[p] = fmaf(xv.x, w0.y, a1[p]);
            a0[p] = fmaf(xv.y, w1.x, a0[p]); a1[p] = fmaf(xv.y, w1.y, a1[p]);
            a0[p] = fmaf(xv.z, w2.x, a0[p]); a1[p] = fmaf(xv.z, w2.y, a1[p]);
            a0[p] = fmaf(xv.w, w3.x, a0[p]); a1[p] = fmaf(xv.w, w3.y, a1[p]);
        }
    }
#pragma unroll
    for (int p = 0; p < 16; p++) {
        float2 v = make_float2(a0[p], a1[p]);
        *reinterpret_cast<float2*>(&d_z[(pix0 + row * 16 + p) * DI + 2 * col]) = v;
    }
}

// ---------- K2: depthwise 3x3 conv + bias + silu ----------
__global__ void k2_conv(const float* __restrict__ wc, const float* __restrict__ bcv) {
    int c = threadIdx.x;               // 0..191
    int seg = blockIdx.x;              // 4096
    int b = seg >> 9;
    int h = (seg >> 3) & 63;
    int w0 = (seg & 7) << 3;
    float wreg[9];
#pragma unroll
    for (int i = 0; i < 9; i++) wreg[i] = wc[i * DI + c];
    float row[3][10];
#pragma unroll
    for (int dh = 0; dh < 3; dh++) {
        int hh = h + dh - 1;
        bool hok = (hh >= 0 && hh < 64);
#pragma unroll
        for (int dw = 0; dw < 10; dw++) {
            int ww = w0 + dw - 1;
            row[dh][dw] = (hok && ww >= 0 && ww < 64)
                ? d_z[(((b << 12) + (hh << 6) + ww)) * DI + c] : 0.f;
        }
    }
    float bias = bcv[c];
#pragma unroll
    for (int q = 0; q < 8; q++) {
        float acc = bias;
#pragma unroll
        for (int dh = 0; dh < 3; dh++)
#pragma unroll
            for (int dw = 0; dw < 3; dw++)
                acc = fmaf(row[dh][q + dw], wreg[dh * 3 + dw], acc);
        int pix = (b << 12) + (h << 6) + w0 + q;
        d_xi[pix * DI + c] = acc / (1.f + expf(-acc));
    }
}

// ---------- K3: projection GEMM via mma.sync tf32 ----------
#define SAK 196
#define SBK 196
#define SA_FLOATS (128 * SAK)
#define SB_FLOATS (152 * SBK)
#define K3_SMEM_BYTES ((SA_FLOATS + SB_FLOATS + 64) * 4)

__global__ __launch_bounds__(256) void k3_mma(const float* __restrict__ xpw,
                                              const float* __restrict__ Alogs,
                                              const float* __restrict__ dtb) {
    extern __shared__ __align__(16) uint32_t smem[];
    uint32_t* sA = smem;
    uint32_t* sB = smem + SA_FLOATS;
    float* sAk  = reinterpret_cast<float*>(smem + SA_FLOATS + SB_FLOATS);
    float* sdtb = sAk + KRR;

    int t = threadIdx.x;                 // 256
    int wid = t >> 5, lane = t & 31;
    int g = lane >> 2, tg = lane & 3;

    int pix0 = blockIdx.x * 128;
    int b = pix0 >> 12;
    int l0 = pix0 & 4095;

    if (t < KRR) { sAk[t] = -expf(Alogs[t]); sdtb[t] = dtb[t]; }

    {
        const float4* src = reinterpret_cast<const float4*>(d_xi + pix0 * DI);
        for (int idx = t; idx < 128 * 48; idx += 256) {
            int row = idx / 48, c4 = idx % 48;
            float4 v = src[idx];
            uint4 tv = make_uint4(f2tf32(v.x), f2tf32(v.y), f2tf32(v.z), f2tf32(v.w));
            *reinterpret_cast<uint4*>(&sA[row * SAK + c4 * 4]) = tv;
        }
    }
    {
        const float4* src = reinterpret_cast<const float4*>(xpw);
        for (int idx = t; idx < 152 * 48; idx += 256) {
            int n = idx / 48, c4 = idx % 48;
            float4 v = src[idx];
            uint4 tv = make_uint4(f2tf32(v.x), f2tf32(v.y), f2tf32(v.z), f2tf32(v.w));
            *reinterpret_cast<uint4*>(&sB[n * SBK + c4 * 4]) = tv;
        }
    }
    __syncthreads();

    int m0 = wid * 16;
    int row0 = m0 + g, row1 = m0 + g + 8;
    float cacc[19][4];
#pragma unroll
    for (int nt = 0; nt < 19; nt++)
#pragma unroll
        for (int j = 0; j < 4; j++) cacc[nt][j] = 0.f;

    const uint32_t* pa0 = &sA[row0 * SAK + tg];
    const uint32_t* pa1 = &sA[row1 * SAK + tg];
#pragma unroll 4
    for (int k0 = 0; k0 < 192; k0 += 8) {
        uint32_t a0 = pa0[k0], a2 = pa0[k0 + 4];
        uint32_t a1 = pa1[k0], a3 = pa1[k0 + 4];
        const uint32_t* pb = &sB[g * SBK + k0 + tg];
#pragma unroll
        for (int nt = 0; nt < 19; nt++) {
            uint32_t b0 = pb[nt * 8 * SBK];
            uint32_t b1 = pb[nt * 8 * SBK + 4];
            asm volatile(
                "mma.sync.aligned.m16n8k8.row.col.f32.tf32.tf32.f32 "
                "{%0,%1,%2,%3}, {%4,%5,%6,%7}, {%8,%9}, {%0,%1,%2,%3};"
                : "+f"(cacc[nt][0]), "+f"(cacc[nt][1]), "+f"(cacc[nt][2]), "+f"(cacc[nt][3])
                : "r"(a0), "r"(a1), "r"(a2), "r"(a3), "r"(b0), "r"(b1));
        }
    }

#pragma unroll
    for (int nt = 0; nt < 19; nt++) {
        int kc = nt * 8 + 2 * tg;
        int k = kc / CPROJ;
        int c = kc - k * CPROJ;
#pragma unroll
        for (int hh = 0; hh < 2; hh++) {
            int row = (hh == 0) ? row0 : row1;
            float v0 = cacc[nt][2 * hh + 0], v1 = cacc[nt][2 * hh + 1];
            int pos = sigma_k(k, l0 + row);
            if (c < RR) {
                float A0 = sAk[k * RR + c],     tb0 = sdtb[k * RR + c];
                float A1 = sAk[k * RR + c + 1], tb1 = sdtb[k * RR + c + 1];
                float x0 = v0 + tb0, x1 = v1 + tb1;
                float dt0 = (x0 > 20.f) ? x0 : log1pf(expf(x0));
                float dt1 = (x1 > 20.f) ? x1 : log1pf(expf(x1));
                float4 w = make_float4(dt0, expf(dt0 * A0), dt1, expf(dt1 * A1));
                *reinterpret_cast<float4*>(&d_dtdk[((b * LL + pos) * KK + k) * RR + c]) = w;
            } else {
                *reinterpret_cast<float2*>(&d_BC[((b * LL + pos) * KK + k) * 32 + (c - RR)]) =
                    make_float2(v0, v1);
            }
        }
    }
}

// ---------- K4A: staged u + f32x2 state pairs ----------
__global__ __launch_bounds__(192) void k4_scanA(const float* __restrict__ Ds) {
    __shared__ __align__(16) float4 sBC[TT * 8];   // 8KB
    __shared__ float2 sdt[TT * RR];                // 3KB
    __shared__ float  su[32 * DI];                 // 24KB
    int bx = blockIdx.x;                 // 2048 = b(8) * k(4) * chunk(64)
    int chunk = bx & 63, k = (bx >> 6) & 3, b = bx >> 8;
    int t = threadIdx.x;
    int warp = t >> 5, lane = t & 31;
    int l0 = chunk * TT;

    const float4* bc4 = reinterpret_cast<const float4*>(d_BC);
    int g4 = ((b * LL + l0) * KK + k) * 8;
    for (int j = t; j < TT * 8; j += 192) {
        int s = j >> 3, w = j & 7;
        sBC[j] = bc4[g4 + s * KK * 8 + w];
    }
    int gd = ((b * LL + l0) * KK + k) * RR;
    for (int j = t; j < TT * RR; j += 192) {
        int s = j / RR, r = j % RR;
        sdt[j] = d_dtdk[gd + s * KK * RR + r];
    }

    int ubase, ustride;
    if (k == 0)      { ubase = l0;        ustride = 1;   }
    else if (k == 1) { ubase = chunk;     ustride = 64;  }
    else if (k == 2) { ubase = 4095 - l0; ustride = -1;  }
    else             { ubase = 4095 - chunk; ustride = -64; }

    int r = warp;  // 0..5
    int sl = b * KRR + k * RR + r;
    float Dd = Ds[(k * RR + r) * 32 + lane];

    ull hp[8];
#pragma unroll
    for (int n = 0; n < 8; n++) hp[n] = 0ULL;
    float P = 1.f;
    int ysIdx = ((b * LL + l0) * KK + k) * 192 + r * 32 + lane;
    int pIdx  = sl * LL + l0;

    const float* ubp = d_xi + (long)(b * LL + ubase) * DI + t;
    long ustepL = (long)ustride * DI;
    const ulonglong2* sBC2 = reinterpret_cast<const ulonglong2*>(sBC);

#pragma unroll
    for (int half = 0; half < 2; half++) {
        __syncthreads();
        {
            const float* up = ubp + (long)(half * 32) * ustepL;
#pragma unroll 8
            for (int sl2 = 0; sl2 < 32; sl2++) {
                su[sl2 * DI + t] = *up;
                up += ustepL;
            }
        }
        __syncthreads();

#pragma unroll 2
        for (int s2 = 0; s2 < 32; s2++) {
            int s = half * 32 + s2;
            float u = su[s2 * DI + r * 32 + lane];
            float2 dd = sdt[s * RR + r];
            ulonglong2 b01 = sBC2[s * 8 + 0], b23 = sBC2[s * 8 + 1];
            ulonglong2 b45 = sBC2[s * 8 + 2], b67 = sBC2[s * 8 + 3];
            ulonglong2 c01 = sBC2[s * 8 + 4], c23 = sBC2[s * 8 + 5];
            ulonglong2 c45 = sBC2[s * 8 + 6], c67 = sBC2[s * 8 + 7];
            ull Bp[8] = {b01.x, b01.y, b23.x, b23.y, b45.x, b45.y, b67.x, b67.y};
            ull Cp[8] = {c01.x, c01.y, c23.x, c23.y, c45.x, c45.y, c67.x, c67.y};
            ull dkb = bcast2(dd.y);
            ull xub = bcast2(dd.x * u);
            ull yp = 0ULL;
#pragma unroll
            for (int n = 0; n < 8; n++) {
                hp[n] = fma2(dkb, hp[n], mul2(xub, Bp[n]));
                yp = fma2(hp[n], Cp[n], yp);
            }
            P *= dd.y;
            float2 yy = unpk(yp);
            d_ys[ysIdx] = fmaf(u, Dd, yy.x + yy.y);
            if (lane == 0) d_P[pIdx] = P;
            ysIdx += KK * 192; pIdx += 1;
        }
    }
    ulonglong2* hout = reinterpret_cast<ulonglong2*>(d_h + ((sl * NCH + chunk) * 32 + lane) * NN);
    hout[0] = make_ulonglong2(hp[0], hp[1]);
    hout[1] = make_ulonglong2(hp[2], hp[3]);
    hout[2] = make_ulonglong2(hp[4], hp[5]);
    hout[3] = make_ulonglong2(hp[6], hp[7]);
}

// ---------- K4B: sequential carry across chunks (single prefetch) ----------
__global__ void k4_scanB() {
    int wid = (blockIdx.x * blockDim.x + threadIdx.x) >> 5;  // 0..191
    int lane = threadIdx.x & 31;
    float h0[NN];
#pragma unroll
    for (int n = 0; n < NN; n++) h0[n] = 0.f;

    const float4* src = reinterpret_cast<const float4*>(d_h + ((wid * NCH) * 32 + lane) * NN);
    float4 a0 = src[0], a1 = src[1], a2 = src[2], a3 = src[3];
    float Dc = d_P[wid * LL + TT - 1];

    for (int c = 0; c < NCH; c++) {
        float4 n0, n1, n2, n3; float Dn = 0.f;
        if (c + 1 < NCH) {
            const float4* s2 = reinterpret_cast<const float4*>(
                d_h + ((wid * NCH + c + 1) * 32 + lane) * NN);
            n0 = s2[0]; n1 = s2[1]; n2 = s2[2]; n3 = s2[3];
            Dn = d_P[wid * LL + (c + 1) * TT + TT - 1];
        } else {
            n0 = n1 = n2 = n3 = make_float4(0.f, 0.f, 0.f, 0.f);
        }
        float4* dst = reinterpret_cast<float4*>(d_h0 + ((wid * NCH + c) * 32 + lane) * NN);
        dst[0] = make_float4(h0[0], h0[1], h0[2], h0[3]);
        dst[1] = make_float4(h0[4], h0[5], h0[6], h0[7]);
        dst[2] = make_float4(h0[8], h0[9], h0[10], h0[11]);
        dst[3] = make_float4(h0[12], h0[13], h0[14], h0[15]);
        float av[NN] = {a0.x,a0.y,a0.z,a0.w, a1.x,a1.y,a1.z,a1.w,
                        a2.x,a2.y,a2.z,a2.w, a3.x,a3.y,a3.z,a3.w};
#pragma unroll
        for (int n = 0; n < NN; n++) h0[n] = fmaf(Dc, h0[n], av[n]);
        a0 = n0; a1 = n1; a2 = n2; a3 = n3; Dc = Dn;
    }
}

// ---------- K4C: fixup ys += P_l * (h0 . C_l); f32x2 ----------
__global__ __launch_bounds__(192) void k4_scanC() {
    __shared__ __align__(16) float4 sC[TT * 4];  // 4KB
    __shared__ float sP[RR * TT];                // 1.5KB
    int bx = blockIdx.x;
    int chunk = bx & 63, k = (bx >> 6) & 3, b = bx >> 8;
    int t = threadIdx.x;
    int warp = t >> 5, lane = t & 31;
    int l0 = chunk * TT;

    const float4* bc4 = reinterpret_cast<const float4*>(d_BC);
    int g4 = ((b * LL + l0) * KK + k) * 8;
    for (int j = t; j < TT * 4; j += 192) {
        int s = j >> 2, w = j & 3;
        sC[j] = bc4[g4 + s * KK * 8 + 4 + w];
    }
    for (int j = t; j < RR * TT; j += 192) {
        int r = j / TT, s = j % TT;
        sP[j] = d_P[(b * KRR + k * RR + r) * LL + l0 + s];
    }
    __syncthreads();

    int r = warp;
    int sl = b * KRR + k * RR + r;
    const ulonglong2* hp2 = reinterpret_cast<const ulonglong2*>(
        d_h0 + ((sl * NCH + chunk) * 32 + lane) * NN);
    ulonglong2 h01 = hp2[0], h23 = hp2[1], h45 = hp2[2], h67 = hp2[3];
    ull h0p[8] = {h01.x, h01.y, h23.x, h23.y, h45.x, h45.y, h67.x, h67.y};

    const ulonglong2* sC2 = reinterpret_cast<const ulonglong2*>(sC);
    int ysIdx = ((b * LL + l0) * KK + k) * 192 + r * 32 + lane;
#pragma unroll 2
    for (int s = 0; s < TT; s++) {
        ulonglong2 c01 = sC2[s * 4 + 0], c23 = sC2[s * 4 + 1];
        ulonglong2 c45 = sC2[s * 4 + 2], c67 = sC2[s * 4 + 3];
        ull Cp[8] = {c01.x, c01.y, c23.x, c23.y, c45.x, c45.y, c67.x, c67.y};
        ull corrp = 0ULL;
#pragma unroll
        for (int n = 0; n < 8; n++) corrp = fma2(h0p[n], Cp[n], corrp);
        float2 cc = unpk(corrp);
        d_ys[ysIdx] = fmaf(sP[r * TT + s], cc.x + cc.y, d_ys[ysIdx]);
        ysIdx += KK * 192;
    }
}

// ---------- K5: cross-merge + LayerNorm + out-proj ----------
__global__ __launch_bounds__(192) void k5_out(const float* __restrict__ lng,
                                              const float* __restrict__ lnb,
                                              const float* __restrict__ wout,
                                              float* __restrict__ out) {
    __shared__ __align__(16) float sy[32 * DI];   // 24KB
    __shared__ float smu[32], srs[32];
    int t = threadIdx.x;  // 192
    int pb = blockIdx.x * 32;    // 32 | 4096: never crosses batch
    int b = pb >> 12;
    int lbase = pb & 4095;

    for (int p = 0; p < 32; p++) {
        int l = lbase + p;
        float v = 0.f;
#pragma unroll
        for (int k = 0; k < KK; k++) {
            int pos = sigma_k(k, l);
            v += d_ys[((b * LL + pos) * KK + k) * 192 + t];
        }
        sy[p * DI + t] = v;
    }
    __syncthreads();

    int warp = t >> 5, lane = t & 31;
    for (int p = warp; p < 32; p += 6) {
        float s1 = 0.f, s2 = 0.f;
#pragma unroll
        for (int j = 0; j < 6; j++) {
            float v = sy[p * DI + lane + j * 32];
            s1 += v; s2 = fmaf(v, v, s2);
        }
#pragma unroll
        for (int o = 16; o > 0; o >>= 1) {
            s1 += __shfl_down_sync(0xffffffffu, s1, o);
            s2 += __shfl_down_sync(0xffffffffu, s2, o);
        }
        if (lane == 0) {
            float mu = s1 * (1.f / DI);
            float var = s2 * (1.f / DI) - mu * mu;
            smu[p] = mu;
            srs[p] = rsqrtf(var + 1e-5f);
        }
    }
    __syncthreads();

    float g = lng[t], be = lnb[t];
    for (int p = 0; p < 32; p++)
        sy[p * DI + t] = (sy[p * DI + t] - smu[p]) * srs[p] * g + be;
    __syncthreads();

    const float4* sy4 = reinterpret_cast<const float4*>(sy);
    int row = t / 48;     // 0..3 -> pixels row*8 .. +7
    int col = t % 48;     // outputs 2col, 2col+1
    float a0[8], a1[8];
#pragma unroll
    for (int q = 0; q < 8; q++) { a0[q] = 0.f; a1[q] = 0.f; }
    for (int c4 = 0; c4 < DI / 4; c4++) {
        float2 w0 = *reinterpret_cast<const float2*>(&wout[(c4 * 4 + 0) * 96 + 2 * col]);
        float2 w1 = *reinterpret_cast<const float2*>(&wout[(c4 * 4 + 1) * 96 + 2 * col]);
        float2 w2 = *reinterpret_cast<const float2*>(&wout[(c4 * 4 + 2) * 96 + 2 * col]);
        float2 w3 = *reinterpret_cast<const float2*>(&wout[(c4 * 4 + 3) * 96 + 2 * col]);
#pragma unroll
        for (int q = 0; q < 8; q++) {
            float4 sv = sy4[(row * 8 + q) * (DI / 4) + c4];
            a0[q] = fmaf(sv.x, w0.x, a0[q]); a1[q] = fmaf(sv.x, w0.y, a1[q]);
            a0[q] = fmaf(sv.y, w1.x, a0[q]); a1[q] = fmaf(sv.y, w1.y, a1[q]);
            a0[q] = fmaf(sv.z, w2.x, a0[q]); a1[q] = fmaf(sv.z, w2.y, a1[q]);
            a0[q] = fmaf(sv.w, w3.x, a0[q]); a1[q] = fmaf(sv.w, w3.y, a1[q]);
        }
    }
#pragma unroll
    for (int q = 0; q < 8; q++) {
        float2 v = make_float2(a0[q], a1[q]);
        *reinterpret_cast<float2*>(&out[(pb + row * 8 + q) * 96 + 2 * col]) = v;
    }
}

extern "C" void kernel_launch(void* const* d_in, const int* in_sizes, int n_in,
                              void* d_out, int out_size) {
    const float* x    = (const float*)d_in[0];
    const float* w_in = (const float*)d_in[1];
    const float* wconv= (const float*)d_in[2];
    const float* bconv= (const float*)d_in[3];
    const float* xpw  = (const float*)d_in[4];
    const float* Alog = (const float*)d_in[5];
    const float* Ds   = (const float*)d_in[6];
    const float* dtb  = (const float*)d_in[7];
    const float* lng  = (const float*)d_in[8];
    const float* lnb  = (const float*)d_in[9];
    const float* wout = (const float*)d_in[10];
    float* out = (float*)d_out;

    cudaFuncSetAttribute(k3_mma, cudaFuncAttributeMaxDynamicSharedMemorySize, K3_SMEM_BYTES);

    k1_inproj<<<BB * LL / 32, 192>>>(x, w_in);
    k2_conv<<<BB * LL / 8, DI>>>(wconv, bconv);
    k3_mma<<<BB * LL / 128, 256, K3_SMEM_BYTES>>>(xpw, Alog, dtb);
    k4_scanA<<<BB * KK * NCH, 192>>>(Ds);
    k4_scanB<<<24, 256>>>();
    k4_scanC<<<BB * KK * NCH, 192>>>();
    k5_out<<<BB * LL / 32, 192>>>(lng, lnb, wout, out);
}

// round 16
// speedup vs baseline: 1.0699x; 1.0252x over previous
#include <cuda_runtime.h>
#include <math.h>
#include <stdint.h>

#define BB 8
#define LL 4096
#define CIN 96
#define DI 192
#define KK 4
#define RR 6
#define NN 16
#define KRR 24
#define NCH 64
#define TT 64
#define CPROJ 38
#define KC 152   // KK*CPROJ
#define NG 8     // chunk groups
#define GS 8     // chunks per group

typedef unsigned long long ull;
__device__ __forceinline__ ull fma2(ull a, ull b, ull c) {
    ull d; asm("fma.rn.f32x2 %0, %1, %2, %3;" : "=l"(d) : "l"(a), "l"(b), "l"(c)); return d;
}
__device__ __forceinline__ ull mul2(ull a, ull b) {
    ull d; asm("mul.rn.f32x2 %0, %1, %2;" : "=l"(d) : "l"(a), "l"(b)); return d;
}
__device__ __forceinline__ ull bcast2(float x) {
    ull r; asm("mov.b64 %0, {%1, %1};" : "=l"(r) : "f"(x)); return r;
}
__device__ __forceinline__ float2 unpk(ull v) {
    float a, b; asm("mov.b64 {%0, %1}, %2;" : "=f"(a), "=f"(b) : "l"(v)); return make_float2(a, b);
}

// scratch (static device globals; no allocation)
__device__ float  d_z [BB*LL*DI];
__device__ float  d_xi[BB*LL*DI];
__device__ float  d_BC[BB*LL*KK*32];          // per (b,l,k): B[0..15], C[16..31]
__device__ float2 d_dtdk[BB*LL*KK*RR];        // (dt, decay)
__device__ float  d_ys[BB*LL*KK*RR*32];
__device__ float  d_P [BB*KRR*LL];            // cumulative within-chunk decay
__device__ float  d_h [BB*KRR*NCH*32*NN];     // chunk-end states (from A)
__device__ float  d_h0[BB*KRR*NCH*32*NN];     // chunk-start states (B1 local, fixed by B3)
__device__ float  d_hg[BB*KRR*NG*32*NN];      // group-end local states
__device__ float  d_cr[BB*KRR*NG*32*NN];      // group carry-in states
__device__ float  d_Q [BB*KRR*NCH];           // within-group prefix decay per chunk
__device__ float  d_Dg[BB*KRR*NG];            // group decay product

__device__ __forceinline__ int tau_idx(int l) { return ((l & 63) << 6) | (l >> 6); }
__device__ __forceinline__ int sigma_k(int k, int l) {
    int t = (k & 1) ? tau_idx(l) : l;
    return (k >= 2) ? (4095 - t) : t;
}
__device__ __forceinline__ uint32_t f2tf32(float v) {
    uint32_t o; asm("cvt.rna.tf32.f32 %0, %1;" : "=r"(o) : "f"(v)); return o;
}

// ---------- K1: z = x @ w_in (scalar float4, 16px x 2out) ----------
__global__ __launch_bounds__(192) void k1_inproj(const float* __restrict__ x,
                                                 const float* __restrict__ w_in) {
    __shared__ __align__(16) float sx[32 * CIN];
    int pix0 = blockIdx.x * 32;
    int t = threadIdx.x;  // 192
    const float4* xg = reinterpret_cast<const float4*>(x + pix0 * CIN);
    float4* sx4s = reinterpret_cast<float4*>(sx);
    for (int i = t; i < 32 * CIN / 4; i += 192) sx4s[i] = xg[i];
    __syncthreads();
    const float4* sx4 = reinterpret_cast<const float4*>(sx);
    int row = t / 96;      // 0..1 -> pixels row*16 .. +15
    int col = t % 96;      // outputs 2col, 2col+1
    float a0[16], a1[16];
#pragma unroll
    for (int p = 0; p < 16; p++) { a0[p] = 0.f; a1[p] = 0.f; }
    for (int i4 = 0; i4 < CIN / 4; i4++) {
        float2 w0 = *reinterpret_cast<const float2*>(&w_in[(i4 * 4 + 0) * DI + 2 * col]);
        float2 w1 = *reinterpret_cast<const float2*>(&w_in[(i4 * 4 + 1) * DI + 2 * col]);
        float2 w2 = *reinterpret_cast<const float2*>(&w_in[(i4 * 4 + 2) * DI + 2 * col]);
        float2 w3 = *reinterpret_cast<const float2*>(&w_in[(i4 * 4 + 3) * DI + 2 * col]);
#pragma unroll
        for (int p = 0; p < 16; p++) {
            float4 xv = sx4[(row * 16 + p) * (CIN / 4) + i4];
            a0[p] = fmaf(xv.x, w0.x, a0[p]); a1[p] = fmaf(xv.x, w0.y, a1[p]);
            a0[p] = fmaf(xv.y, w1.x, a0[p]); a1[p] = fmaf(xv.y, w1.y, a1[p]);
            a0[p] = fmaf(xv.z, w2.x, a0[p]); a1[p] = fmaf(xv.z, w2.y, a1[p]);
            a0[p] = fmaf(xv.w, w3.x, a0[p]); a1[p] = fmaf(xv.w, w3.y, a1[p]);
        }
    }
#pragma unroll
    for (int p = 0; p < 16; p++) {
        float2 v = make_float2(a0[p], a1[p]);
        *reinterpret_cast<float2*>(&d_z[(pix0 + row * 16 + p) * DI + 2 * col]) = v;
    }
}

// ---------- K2: depthwise 3x3 conv + bias + silu ----------
__global__ void k2_conv(const float* __restrict__ wc, const float* __restrict__ bcv) {
    int c = threadIdx.x;               // 0..191
    int seg = blockIdx.x;              // 4096
    int b = seg >> 9;
    int h = (seg >> 3) & 63;
    int w0 = (seg & 7) << 3;
    float wreg[9];
#pragma unroll
    for (int i = 0; i < 9; i++) wreg[i] = wc[i * DI + c];
    float row[3][10];
#pragma unroll
    for (int dh = 0; dh < 3; dh++) {
        int hh = h + dh - 1;
        bool hok = (hh >= 0 && hh < 64);
#pragma unroll
        for (int dw = 0; dw < 10; dw++) {
            int ww = w0 + dw - 1;
            row[dh][dw] = (hok && ww >= 0 && ww < 64)
                ? d_z[(((b << 12) + (hh << 6) + ww)) * DI + c] : 0.f;
        }
    }
    float bias = bcv[c];
#pragma unroll
    for (int q = 0; q < 8; q++) {
        float acc = bias;
#pragma unroll
        for (int dh = 0; dh < 3; dh++)
#pragma unroll
            for (int dw = 0; dw < 3; dw++)
                acc = fmaf(row[dh][q + dw], wreg[dh * 3 + dw], acc);
        int pix = (b << 12) + (h << 6) + w0 + q;
        d_xi[pix * DI + c] = acc / (1.f + expf(-acc));
    }
}

// ---------- K3: projection GEMM via mma.sync tf32 ----------
#define SAK 196
#define SBK 196
#define SA_FLOATS (128 * SAK)
#define SB_FLOATS (152 * SBK)
#define K3_SMEM_BYTES ((SA_FLOATS + SB_FLOATS + 64) * 4)

__global__ __launch_bounds__(256) void k3_mma(const float* __restrict__ xpw,
                                              const float* __restrict__ Alogs,
                                              const float* __restrict__ dtb) {
    extern __shared__ __align__(16) uint32_t smem[];
    uint32_t* sA = smem;
    uint32_t* sB = smem + SA_FLOATS;
    float* sAk  = reinterpret_cast<float*>(smem + SA_FLOATS + SB_FLOATS);
    float* sdtb = sAk + KRR;

    int t = threadIdx.x;                 // 256
    int wid = t >> 5, lane = t & 31;
    int g = lane >> 2, tg = lane & 3;

    int pix0 = blockIdx.x * 128;
    int b = pix0 >> 12;
    int l0 = pix0 & 4095;

    if (t < KRR) { sAk[t] = -expf(Alogs[t]); sdtb[t] = dtb[t]; }

    {
        const float4* src = reinterpret_cast<const float4*>(d_xi + pix0 * DI);
        for (int idx = t; idx < 128 * 48; idx += 256) {
            int row = idx / 48, c4 = idx % 48;
            float4 v = src[idx];
            uint4 tv = make_uint4(f2tf32(v.x), f2tf32(v.y), f2tf32(v.z), f2tf32(v.w));
            *reinterpret_cast<uint4*>(&sA[row * SAK + c4 * 4]) = tv;
        }
    }
    {
        const float4* src = reinterpret_cast<const float4*>(xpw);
        for (int idx = t; idx < 152 * 48; idx += 256) {
            int n = idx / 48, c4 = idx % 48;
            float4 v = src[idx];
            uint4 tv = make_uint4(f2tf32(v.x), f2tf32(v.y), f2tf32(v.z), f2tf32(v.w));
            *reinterpret_cast<uint4*>(&sB[n * SBK + c4 * 4]) = tv;
        }
    }
    __syncthreads();

    int m0 = wid * 16;
    int row0 = m0 + g, row1 = m0 + g + 8;
    float cacc[19][4];
#pragma unroll
    for (int nt = 0; nt < 19; nt++)
#pragma unroll
        for (int j = 0; j < 4; j++) cacc[nt][j] = 0.f;

    const uint32_t* pa0 = &sA[row0 * SAK + tg];
    const uint32_t* pa1 = &sA[row1 * SAK + tg];
#pragma unroll 4
    for (int k0 = 0; k0 < 192; k0 += 8) {
        uint32_t a0 = pa0[k0], a2 = pa0[k0 + 4];
        uint32_t a1 = pa1[k0], a3 = pa1[k0 + 4];
        const uint32_t* pb = &sB[g * SBK + k0 + tg];
#pragma unroll
        for (int nt = 0; nt < 19; nt++) {
            uint32_t b0 = pb[nt * 8 * SBK];
            uint32_t b1 = pb[nt * 8 * SBK + 4];
            asm volatile(
                "mma.sync.aligned.m16n8k8.row.col.f32.tf32.tf32.f32 "
                "{%0,%1,%2,%3}, {%4,%5,%6,%7}, {%8,%9}, {%0,%1,%2,%3};"
                : "+f"(cacc[nt][0]), "+f"(cacc[nt][1]), "+f"(cacc[nt][2]), "+f"(cacc[nt][3])
                : "r"(a0), "r"(a1), "r"(a2), "r"(a3), "r"(b0), "r"(b1));
        }
    }

#pragma unroll
    for (int nt = 0; nt < 19; nt++) {
        int kc = nt * 8 + 2 * tg;
        int k = kc / CPROJ;
        int c = kc - k * CPROJ;
#pragma unroll
        for (int hh = 0; hh < 2; hh++) {
            int row = (hh == 0) ? row0 : row1;
            float v0 = cacc[nt][2 * hh + 0], v1 = cacc[nt][2 * hh + 1];
            int pos = sigma_k(k, l0 + row);
            if (c < RR) {
                float A0 = sAk[k * RR + c],     tb0 = sdtb[k * RR + c];
                float A1 = sAk[k * RR + c + 1], tb1 = sdtb[k * RR + c + 1];
                float x0 = v0 + tb0, x1 = v1 + tb1;
                float dt0 = (x0 > 20.f) ? x0 : log1pf(expf(x0));
                float dt1 = (x1 > 20.f) ? x1 : log1pf(expf(x1));
                float4 w = make_float4(dt0, expf(dt0 * A0), dt1, expf(dt1 * A1));
                *reinterpret_cast<float4*>(&d_dtdk[((b * LL + pos) * KK + k) * RR + c]) = w;
            } else {
                *reinterpret_cast<float2*>(&d_BC[((b * LL + pos) * KK + k) * 32 + (c - RR)]) =
                    make_float2(v0, v1);
            }
        }
    }
}

// ---------- K4A: staged u + f32x2 state pairs [round-11 exact] ----------
__global__ __launch_bounds__(192) void k4_scanA(const float* __restrict__ Ds) {
    __shared__ __align__(16) float4 sBC[TT * 8];   // 8KB
    __shared__ float2 sdt[TT * RR];                // 3KB
    __shared__ float  su[32 * DI];                 // 24KB
    int bx = blockIdx.x;                 // 2048 = b(8) * k(4) * chunk(64)
    int chunk = bx & 63, k = (bx >> 6) & 3, b = bx >> 8;
    int t = threadIdx.x;
    int warp = t >> 5, lane = t & 31;
    int l0 = chunk * TT;

    const float4* bc4 = reinterpret_cast<const float4*>(d_BC);
    int g4 = ((b * LL + l0) * KK + k) * 8;
    for (int j = t; j < TT * 8; j += 192) {
        int s = j >> 3, w = j & 7;
        sBC[j] = bc4[g4 + s * KK * 8 + w];
    }
    int gd = ((b * LL + l0) * KK + k) * RR;
    for (int j = t; j < TT * RR; j += 192) {
        int s = j / RR, r = j % RR;
        sdt[j] = d_dtdk[gd + s * KK * RR + r];
    }

    int ubase, ustride;
    if (k == 0)      { ubase = l0;        ustride = 1;   }
    else if (k == 1) { ubase = chunk;     ustride = 64;  }
    else if (k == 2) { ubase = 4095 - l0; ustride = -1;  }
    else             { ubase = 4095 - chunk; ustride = -64; }

    int r = warp;  // 0..5
    int sl = b * KRR + k * RR + r;
    float Dd = Ds[(k * RR + r) * 32 + lane];

    ull hp[8];
#pragma unroll
    for (int n = 0; n < 8; n++) hp[n] = 0ULL;
    float P = 1.f;
    int ysIdx = ((b * LL + l0) * KK + k) * 192 + r * 32 + lane;
    int pIdx  = sl * LL + l0;

    const float* ubp = d_xi + (long)(b * LL + ubase) * DI + t;
    long ustepL = (long)ustride * DI;
    const ulonglong2* sBC2 = reinterpret_cast<const ulonglong2*>(sBC);

#pragma unroll
    for (int half = 0; half < 2; half++) {
        __syncthreads();
        {
            const float* up = ubp + (long)(half * 32) * ustepL;
#pragma unroll 8
            for (int sl2 = 0; sl2 < 32; sl2++) {
                su[sl2 * DI + t] = *up;
                up += ustepL;
            }
        }
        __syncthreads();

#pragma unroll 2
        for (int s2 = 0; s2 < 32; s2++) {
            int s = half * 32 + s2;
            float u = su[s2 * DI + r * 32 + lane];
            float2 dd = sdt[s * RR + r];
            ulonglong2 b01 = sBC2[s * 8 + 0], b23 = sBC2[s * 8 + 1];
            ulonglong2 b45 = sBC2[s * 8 + 2], b67 = sBC2[s * 8 + 3];
            ulonglong2 c01 = sBC2[s * 8 + 4], c23 = sBC2[s * 8 + 5];
            ulonglong2 c45 = sBC2[s * 8 + 6], c67 = sBC2[s * 8 + 7];
            ull Bp[8] = {b01.x, b01.y, b23.x, b23.y, b45.x, b45.y, b67.x, b67.y};
            ull Cp[8] = {c01.x, c01.y, c23.x, c23.y, c45.x, c45.y, c67.x, c67.y};
            ull dkb = bcast2(dd.y);
            ull xub = bcast2(dd.x * u);
            ull yp = 0ULL;
#pragma unroll
            for (int n = 0; n < 8; n++) {
                hp[n] = fma2(dkb, hp[n], mul2(xub, Bp[n]));
                yp = fma2(hp[n], Cp[n], yp);
            }
            P *= dd.y;
            float2 yy = unpk(yp);
            d_ys[ysIdx] = fmaf(u, Dd, yy.x + yy.y);
            if (lane == 0) d_P[pIdx] = P;
            ysIdx += KK * 192; pIdx += 1;
        }
    }
    ulonglong2* hout = reinterpret_cast<ulonglong2*>(d_h + ((sl * NCH + chunk) * 32 + lane) * NN);
    hout[0] = make_ulonglong2(hp[0], hp[1]);
    hout[1] = make_ulonglong2(hp[2], hp[3]);
    hout[2] = make_ulonglong2(hp[4], hp[5]);
    hout[3] = make_ulonglong2(hp[6], hp[7]);
}

// ---------- K4B1: group-local carry (8 chunks per warp, parallel over 1536 warps) ----------
__global__ __launch_bounds__(256) void k4_b1() {
    int gw = (blockIdx.x * blockDim.x + threadIdx.x) >> 5;  // 0..1535
    int lane = threadIdx.x & 31;
    int sl = gw >> 3, g = gw & 7;

    float h[NN];
#pragma unroll
    for (int n = 0; n < NN; n++) h[n] = 0.f;
    float q = 1.f;

#pragma unroll
    for (int j = 0; j < GS; j++) {
        int c = g * GS + j;
        // write group-local chunk-start state
        float4* dst = reinterpret_cast<float4*>(d_h0 + ((sl * NCH + c) * 32 + lane) * NN);
        dst[0] = make_float4(h[0], h[1], h[2], h[3]);
        dst[1] = make_float4(h[4], h[5], h[6], h[7]);
        dst[2] = make_float4(h[8], h[9], h[10], h[11]);
        dst[3] = make_float4(h[12], h[13], h[14], h[15]);
        if (lane == 0) d_Q[sl * NCH + c] = q;
        const float4* src = reinterpret_cast<const float4*>(d_h + ((sl * NCH + c) * 32 + lane) * NN);
        float4 a0 = src[0], a1 = src[1], a2 = src[2], a3 = src[3];
        float P = d_P[sl * LL + c * TT + TT - 1];
        float av[NN] = {a0.x,a0.y,a0.z,a0.w, a1.x,a1.y,a1.z,a1.w,
                        a2.x,a2.y,a2.z,a2.w, a3.x,a3.y,a3.z,a3.w};
#pragma unroll
        for (int n = 0; n < NN; n++) h[n] = fmaf(P, h[n], av[n]);
        q *= P;
    }
    float4* hg = reinterpret_cast<float4*>(d_hg + ((sl * NG + g) * 32 + lane) * NN);
    hg[0] = make_float4(h[0], h[1], h[2], h[3]);
    hg[1] = make_float4(h[4], h[5], h[6], h[7]);
    hg[2] = make_float4(h[8], h[9], h[10], h[11]);
    hg[3] = make_float4(h[12], h[13], h[14], h[15]);
    if (lane == 0) d_Dg[sl * NG + g] = q;
}

// ---------- K4B2: carry across 8 groups (192 warps, 8 serial steps) ----------
__global__ __launch_bounds__(256) void k4_b2() {
    int sl = (blockIdx.x * blockDim.x + threadIdx.x) >> 5;  // 0..191
    int lane = threadIdx.x & 31;
    float cr[NN];
#pragma unroll
    for (int n = 0; n < NN; n++) cr[n] = 0.f;
#pragma unroll
    for (int g = 0; g < NG; g++) {
        float4* dst = reinterpret_cast<float4*>(d_cr + ((sl * NG + g) * 32 + lane) * NN);
        dst[0] = make_float4(cr[0], cr[1], cr[2], cr[3]);
        dst[1] = make_float4(cr[4], cr[5], cr[6], cr[7]);
        dst[2] = make_float4(cr[8], cr[9], cr[10], cr[11]);
        dst[3] = make_float4(cr[12], cr[13], cr[14], cr[15]);
        const float4* hg = reinterpret_cast<const float4*>(d_hg + ((sl * NG + g) * 32 + lane) * NN);
        float4 a0 = hg[0], a1 = hg[1], a2 = hg[2], a3 = hg[3];
        float Dg = d_Dg[sl * NG + g];
        float av[NN] = {a0.x,a0.y,a0.z,a0.w, a1.x,a1.y,a1.z,a1.w,
                        a2.x,a2.y,a2.z,a2.w, a3.x,a3.y,a3.z,a3.w};
#pragma unroll
        for (int n = 0; n < NN; n++) cr[n] = fmaf(Dg, cr[n], av[n]);
    }
}

// ---------- K4B3: fixup h0[c] += Q_c * carry[group(c)] (12288 warps, parallel) ----------
__global__ __launch_bounds__(256) void k4_b3() {
    int gw = (blockIdx.x * blockDim.x + threadIdx.x) >> 5;  // 0..12287
    int lane = threadIdx.x & 31;
    int sl = gw >> 6, c = gw & 63;
    int g = c >> 3;
    float Q = d_Q[sl * NCH + c];
    const float4* crp = reinterpret_cast<const float4*>(d_cr + ((sl * NG + g) * 32 + lane) * NN);
    float4 c0 = crp[0], c1 = crp[1], c2 = crp[2], c3 = crp[3];
    float4* h0p = reinterpret_cast<float4*>(d_h0 + ((sl * NCH + c) * 32 + lane) * NN);
    float4 h0 = h0p[0], h1 = h0p[1], h2 = h0p[2], h3 = h0p[3];
    h0.x = fmaf(Q, c0.x, h0.x); h0.y = fmaf(Q, c0.y, h0.y);
    h0.z = fmaf(Q, c0.z, h0.z); h0.w = fmaf(Q, c0.w, h0.w);
    h1.x = fmaf(Q, c1.x, h1.x); h1.y = fmaf(Q, c1.y, h1.y);
    h1.z = fmaf(Q, c1.z, h1.z); h1.w = fmaf(Q, c1.w, h1.w);
    h2.x = fmaf(Q, c2.x, h2.x); h2.y = fmaf(Q, c2.y, h2.y);
    h2.z = fmaf(Q, c2.z, h2.z); h2.w = fmaf(Q, c2.w, h2.w);
    h3.x = fmaf(Q, c3.x, h3.x); h3.y = fmaf(Q, c3.y, h3.y);
    h3.z = fmaf(Q, c3.z, h3.z); h3.w = fmaf(Q, c3.w, h3.w);
    h0p[0] = h0; h0p[1] = h1; h0p[2] = h2; h0p[3] = h3;
}

// ---------- K4C: fixup ys += P_l * (h0 . C_l); f32x2 [round-11 exact] ----------
__global__ __launch_bounds__(192) void k4_scanC() {
    __shared__ __align__(16) float4 sC[TT * 4];  // 4KB
    __shared__ float sP[RR * TT];                // 1.5KB
    int bx = blockIdx.x;
    int chunk = bx & 63, k = (bx >> 6) & 3, b = bx >> 8;
    int t = threadIdx.x;
    int warp = t >> 5, lane = t & 31;
    int l0 = chunk * TT;

    const float4* bc4 = reinterpret_cast<const float4*>(d_BC);
    int g4 = ((b * LL + l0) * KK + k) * 8;
    for (int j = t; j < TT * 4; j += 192) {
        int s = j >> 2, w = j & 3;
        sC[j] = bc4[g4 + s * KK * 8 + 4 + w];
    }
    for (int j = t; j < RR * TT; j += 192) {
        int r = j / TT, s = j % TT;
        sP[j] = d_P[(b * KRR + k * RR + r) * LL + l0 + s];
    }
    __syncthreads();

    int r = warp;
    int sl = b * KRR + k * RR + r;
    const ulonglong2* hp2 = reinterpret_cast<const ulonglong2*>(
        d_h0 + ((sl * NCH + chunk) * 32 + lane) * NN);
    ulonglong2 h01 = hp2[0], h23 = hp2[1], h45 = hp2[2], h67 = hp2[3];
    ull h0p[8] = {h01.x, h01.y, h23.x, h23.y, h45.x, h45.y, h67.x, h67.y};

    const ulonglong2* sC2 = reinterpret_cast<const ulonglong2*>(sC);
    int ysIdx = ((b * LL + l0) * KK + k) * 192 + r * 32 + lane;
#pragma unroll 2
    for (int s = 0; s < TT; s++) {
        ulonglong2 c01 = sC2[s * 4 + 0], c23 = sC2[s * 4 + 1];
        ulonglong2 c45 = sC2[s * 4 + 2], c67 = sC2[s * 4 + 3];
        ull Cp[8] = {c01.x, c01.y, c23.x, c23.y, c45.x, c45.y, c67.x, c67.y};
        ull corrp = 0ULL;
#pragma unroll
        for (int n = 0; n < 8; n++) corrp = fma2(h0p[n], Cp[n], corrp);
        float2 cc = unpk(corrp);
        d_ys[ysIdx] = fmaf(sP[r * TT + s], cc.x + cc.y, d_ys[ysIdx]);
        ysIdx += KK * 192;
    }
}

// ---------- K5: cross-merge + LayerNorm + out-proj ----------
__global__ __launch_bounds__(192) void k5_out(const float* __restrict__ lng,
                                              const float* __restrict__ lnb,
                                              const float* __restrict__ wout,
                                              float* __restrict__ out) {
    __shared__ __align__(16) float sy[32 * DI];   // 24KB
    __shared__ float smu[32], srs[32];
    int t = threadIdx.x;  // 192
    int pb = blockIdx.x * 32;    // 32 | 4096: never crosses batch
    int b = pb >> 12;
    int lbase = pb & 4095;

    for (int p = 0; p < 32; p++) {
        int l = lbase + p;
        float v = 0.f;
#pragma unroll
        for (int k = 0; k < KK; k++) {
            int pos = sigma_k(k, l);
            v += d_ys[((b * LL + pos) * KK + k) * 192 + t];
        }
        sy[p * DI + t] = v;
    }
    __syncthreads();

    int warp = t >> 5, lane = t & 31;
    for (int p = warp; p < 32; p += 6) {
        float s1 = 0.f, s2 = 0.f;
#pragma unroll
        for (int j = 0; j < 6; j++) {
            float v = sy[p * DI + lane + j * 32];
            s1 += v; s2 = fmaf(v, v, s2);
        }
#pragma unroll
        for (int o = 16; o > 0; o >>= 1) {
            s1 += __shfl_down_sync(0xffffffffu, s1, o);
            s2 += __shfl_down_sync(0xffffffffu, s2, o);
        }
        if (lane == 0) {
            float mu = s1 * (1.f / DI);
            float var = s2 * (1.f / DI) - mu * mu;
            smu[p] = mu;
            srs[p] = rsqrtf(var + 1e-5f);
        }
    }
    __syncthreads();

    float g = lng[t], be = lnb[t];
    for (int p = 0; p < 32; p++)
        sy[p * DI + t] = (sy[p * DI + t] - smu[p]) * srs[p] * g + be;
    __syncthreads();

    const float4* sy4 = reinterpret_cast<const float4*>(sy);
    int row = t / 48;     // 0..3 -> pixels row*8 .. +7
    int col = t % 48;     // outputs 2col, 2col+1
    float a0[8], a1[8];
#pragma unroll
    for (int q = 0; q < 8; q++) { a0[q] = 0.f; a1[q] = 0.f; }
    for (int c4 = 0; c4 < DI / 4; c4++) {
        float2 w0 = *reinterpret_cast<const float2*>(&wout[(c4 * 4 + 0) * 96 + 2 * col]);
        float2 w1 = *reinterpret_cast<const float2*>(&wout[(c4 * 4 + 1) * 96 + 2 * col]);
        float2 w2 = *reinterpret_cast<const float2*>(&wout[(c4 * 4 + 2) * 96 + 2 * col]);
        float2 w3 = *reinterpret_cast<const float2*>(&wout[(c4 * 4 + 3) * 96 + 2 * col]);
#pragma unroll
        for (int q = 0; q < 8; q++) {
            float4 sv = sy4[(row * 8 + q) * (DI / 4) + c4];
            a0[q] = fmaf(sv.x, w0.x, a0[q]); a1[q] = fmaf(sv.x, w0.y, a1[q]);
            a0[q] = fmaf(sv.y, w1.x, a0[q]); a1[q] = fmaf(sv.y, w1.y, a1[q]);
            a0[q] = fmaf(sv.z, w2.x, a0[q]); a1[q] = fmaf(sv.z, w2.y, a1[q]);
            a0[q] = fmaf(sv.w, w3.x, a0[q]); a1[q] = fmaf(sv.w, w3.y, a1[q]);
        }
    }
#pragma unroll
    for (int q = 0; q < 8; q++) {
        float2 v = make_float2(a0[q], a1[q]);
        *reinterpret_cast<float2*>(&out[(pb + row * 8 + q) * 96 + 2 * col]) = v;
    }
}

extern "C" void kernel_launch(void* const* d_in, const int* in_sizes, int n_in,
                              void* d_out, int out_size) {
    const float* x    = (const float*)d_in[0];
    const float* w_in = (const float*)d_in[1];
    const float* wconv= (const float*)d_in[2];
    const float* bconv= (const float*)d_in[3];
    const float* xpw  = (const float*)d_in[4];
    const float* Alog = (const float*)d_in[5];
    const float* Ds   = (const float*)d_in[6];
    const float* dtb  = (const float*)d_in[7];
    const float* lng  = (const float*)d_in[8];
    const float* lnb  = (const float*)d_in[9];
    const float* wout = (const float*)d_in[10];
    float* out = (float*)d_out;

    cudaFuncSetAttribute(k3_mma, cudaFuncAttributeMaxDynamicSharedMemorySize, K3_SMEM_BYTES);

    k1_inproj<<<BB * LL / 32, 192>>>(x, w_in);
    k2_conv<<<BB * LL / 8, DI>>>(wconv, bconv);
    k3_mma<<<BB * LL / 128, 256, K3_SMEM_BYTES>>>(xpw, Alog, dtb);
    k4_scanA<<<BB * KK * NCH, 192>>>(Ds);
    k4_b1<<<192, 256>>>();
    k4_b2<<<24, 256>>>();
    k4_b3<<<1536, 256>>>();
    k4_scanC<<<BB * KK * NCH, 192>>>();
    k5_out<<<BB * LL / 32, 192>>>(lng, lnb, wout, out);
}

// round 17
// speedup vs baseline: 1.1139x; 1.0412x over previous
#include <cuda_runtime.h>
#include <math.h>
#include <stdint.h>

#define BB 8
#define LL 4096
#define CIN 96
#define DI 192
#define KK 4
#define RR 6
#define NN 16
#define KRR 24
#define NCH 64
#define TT 64
#define CPROJ 38
#define KC 152   // KK*CPROJ
#define NG 8     // chunk groups
#define GS 8     // chunks per group

typedef unsigned long long ull;
__device__ __forceinline__ ull fma2(ull a, ull b, ull c) {
    ull d; asm("fma.rn.f32x2 %0, %1, %2, %3;" : "=l"(d) : "l"(a), "l"(b), "l"(c)); return d;
}
__device__ __forceinline__ ull mul2(ull a, ull b) {
    ull d; asm("mul.rn.f32x2 %0, %1, %2;" : "=l"(d) : "l"(a), "l"(b)); return d;
}
__device__ __forceinline__ ull bcast2(float x) {
    ull r; asm("mov.b64 %0, {%1, %1};" : "=l"(r) : "f"(x)); return r;
}
__device__ __forceinline__ float2 unpk(ull v) {
    float a, b; asm("mov.b64 {%0, %1}, %2;" : "=f"(a), "=f"(b) : "l"(v)); return make_float2(a, b);
}

// scratch (static device globals; no allocation)
__device__ float  d_z [BB*LL*DI];
__device__ float  d_xi[BB*LL*DI];
__device__ float  d_BC[BB*LL*KK*32];          // per (b,l,k): B[0..15], C[16..31]
__device__ float2 d_dtdk[BB*LL*KK*RR];        // (dt, decay)
__device__ float  d_ys[BB*LL*KK*RR*32];
__device__ float  d_P [BB*KRR*LL];            // cumulative within-chunk decay
__device__ float  d_h [BB*KRR*NCH*32*NN];     // chunk-end states (from A)
__device__ float  d_h0[BB*KRR*NCH*32*NN];     // chunk-start states (B1 group-local)
__device__ float  d_hg[BB*KRR*NG*32*NN];      // group-end local states
__device__ float  d_cr[BB*KRR*NG*32*NN];      // group carry-in states
__device__ float  d_Q [BB*KRR*NCH];           // within-group prefix decay per chunk
__device__ float  d_Dg[BB*KRR*NG];            // group decay product

__device__ __forceinline__ int tau_idx(int l) { return ((l & 63) << 6) | (l >> 6); }
__device__ __forceinline__ int sigma_k(int k, int l) {
    int t = (k & 1) ? tau_idx(l) : l;
    return (k >= 2) ? (4095 - t) : t;
}
__device__ __forceinline__ uint32_t f2tf32(float v) {
    uint32_t o; asm("cvt.rna.tf32.f32 %0, %1;" : "=r"(o) : "f"(v)); return o;
}

// ---------- K1: z = x @ w_in (scalar float4, 16px x 2out) ----------
__global__ __launch_bounds__(192) void k1_inproj(const float* __restrict__ x,
                                                 const float* __restrict__ w_in) {
    __shared__ __align__(16) float sx[32 * CIN];
    int pix0 = blockIdx.x * 32;
    int t = threadIdx.x;  // 192
    const float4* xg = reinterpret_cast<const float4*>(x + pix0 * CIN);
    float4* sx4s = reinterpret_cast<float4*>(sx);
    for (int i = t; i < 32 * CIN / 4; i += 192) sx4s[i] = xg[i];
    __syncthreads();
    const float4* sx4 = reinterpret_cast<const float4*>(sx);
    int row = t / 96;      // 0..1 -> pixels row*16 .. +15
    int col = t % 96;      // outputs 2col, 2col+1
    float a0[16], a1[16];
#pragma unroll
    for (int p = 0; p < 16; p++) { a0[p] = 0.f; a1[p] = 0.f; }
    for (int i4 = 0; i4 < CIN / 4; i4++) {
        float2 w0 = *reinterpret_cast<const float2*>(&w_in[(i4 * 4 + 0) * DI + 2 * col]);
        float2 w1 = *reinterpret_cast<const float2*>(&w_in[(i4 * 4 + 1) * DI + 2 * col]);
        float2 w2 = *reinterpret_cast<const float2*>(&w_in[(i4 * 4 + 2) * DI + 2 * col]);
        float2 w3 = *reinterpret_cast<const float2*>(&w_in[(i4 * 4 + 3) * DI + 2 * col]);
#pragma unroll
        for (int p = 0; p < 16; p++) {
            float4 xv = sx4[(row * 16 + p) * (CIN / 4) + i4];
            a0[p] = fmaf(xv.x, w0.x, a0[p]); a1[p] = fmaf(xv.x, w0.y, a1[p]);
            a0[p] = fmaf(xv.y, w1.x, a0[p]); a1[p] = fmaf(xv.y, w1.y, a1[p]);
            a0[p] = fmaf(xv.z, w2.x, a0[p]); a1[p] = fmaf(xv.z, w2.y, a1[p]);
            a0[p] = fmaf(xv.w, w3.x, a0[p]); a1[p] = fmaf(xv.w, w3.y, a1[p]);
        }
    }
#pragma unroll
    for (int p = 0; p < 16; p++) {
        float2 v = make_float2(a0[p], a1[p]);
        *reinterpret_cast<float2*>(&d_z[(pix0 + row * 16 + p) * DI + 2 * col]) = v;
    }
}

// ---------- K2: depthwise 3x3 conv + bias + silu ----------
__global__ void k2_conv(const float* __restrict__ wc, const float* __restrict__ bcv) {
    int c = threadIdx.x;               // 0..191
    int seg = blockIdx.x;              // 4096
    int b = seg >> 9;
    int h = (seg >> 3) & 63;
    int w0 = (seg & 7) << 3;
    float wreg[9];
#pragma unroll
    for (int i = 0; i < 9; i++) wreg[i] = wc[i * DI + c];
    float row[3][10];
#pragma unroll
    for (int dh = 0; dh < 3; dh++) {
        int hh = h + dh - 1;
        bool hok = (hh >= 0 && hh < 64);
#pragma unroll
        for (int dw = 0; dw < 10; dw++) {
            int ww = w0 + dw - 1;
            row[dh][dw] = (hok && ww >= 0 && ww < 64)
                ? d_z[(((b << 12) + (hh << 6) + ww)) * DI + c] : 0.f;
        }
    }
    float bias = bcv[c];
#pragma unroll
    for (int q = 0; q < 8; q++) {
        float acc = bias;
#pragma unroll
        for (int dh = 0; dh < 3; dh++)
#pragma unroll
            for (int dw = 0; dw < 3; dw++)
                acc = fmaf(row[dh][q + dw], wreg[dh * 3 + dw], acc);
        int pix = (b << 12) + (h << 6) + w0 + q;
        d_xi[pix * DI + c] = acc / (1.f + expf(-acc));
    }
}

// ---------- K3: projection GEMM via mma.sync tf32 ----------
#define SAK 196
#define SBK 196
#define SA_FLOATS (128 * SAK)
#define SB_FLOATS (152 * SBK)
#define K3_SMEM_BYTES ((SA_FLOATS + SB_FLOATS + 64) * 4)

__global__ __launch_bounds__(256) void k3_mma(const float* __restrict__ xpw,
                                              const float* __restrict__ Alogs,
                                              const float* __restrict__ dtb) {
    extern __shared__ __align__(16) uint32_t smem[];
    uint32_t* sA = smem;
    uint32_t* sB = smem + SA_FLOATS;
    float* sAk  = reinterpret_cast<float*>(smem + SA_FLOATS + SB_FLOATS);
    float* sdtb = sAk + KRR;

    int t = threadIdx.x;                 // 256
    int wid = t >> 5, lane = t & 31;
    int g = lane >> 2, tg = lane & 3;

    int pix0 = blockIdx.x * 128;
    int b = pix0 >> 12;
    int l0 = pix0 & 4095;

    if (t < KRR) { sAk[t] = -expf(Alogs[t]); sdtb[t] = dtb[t]; }

    {
        const float4* src = reinterpret_cast<const float4*>(d_xi + pix0 * DI);
        for (int idx = t; idx < 128 * 48; idx += 256) {
            int row = idx / 48, c4 = idx % 48;
            float4 v = src[idx];
            uint4 tv = make_uint4(f2tf32(v.x), f2tf32(v.y), f2tf32(v.z), f2tf32(v.w));
            *reinterpret_cast<uint4*>(&sA[row * SAK + c4 * 4]) = tv;
        }
    }
    {
        const float4* src = reinterpret_cast<const float4*>(xpw);
        for (int idx = t; idx < 152 * 48; idx += 256) {
            int n = idx / 48, c4 = idx % 48;
            float4 v = src[idx];
            uint4 tv = make_uint4(f2tf32(v.x), f2tf32(v.y), f2tf32(v.z), f2tf32(v.w));
            *reinterpret_cast<uint4*>(&sB[n * SBK + c4 * 4]) = tv;
        }
    }
    __syncthreads();

    int m0 = wid * 16;
    int row0 = m0 + g, row1 = m0 + g + 8;
    float cacc[19][4];
#pragma unroll
    for (int nt = 0; nt < 19; nt++)
#pragma unroll
        for (int j = 0; j < 4; j++) cacc[nt][j] = 0.f;

    const uint32_t* pa0 = &sA[row0 * SAK + tg];
    const uint32_t* pa1 = &sA[row1 * SAK + tg];
#pragma unroll 4
    for (int k0 = 0; k0 < 192; k0 += 8) {
        uint32_t a0 = pa0[k0], a2 = pa0[k0 + 4];
        uint32_t a1 = pa1[k0], a3 = pa1[k0 + 4];
        const uint32_t* pb = &sB[g * SBK + k0 + tg];
#pragma unroll
        for (int nt = 0; nt < 19; nt++) {
            uint32_t b0 = pb[nt * 8 * SBK];
            uint32_t b1 = pb[nt * 8 * SBK + 4];
            asm volatile(
                "mma.sync.aligned.m16n8k8.row.col.f32.tf32.tf32.f32 "
                "{%0,%1,%2,%3}, {%4,%5,%6,%7}, {%8,%9}, {%0,%1,%2,%3};"
                : "+f"(cacc[nt][0]), "+f"(cacc[nt][1]), "+f"(cacc[nt][2]), "+f"(cacc[nt][3])
                : "r"(a0), "r"(a1), "r"(a2), "r"(a3), "r"(b0), "r"(b1));
        }
    }

#pragma unroll
    for (int nt = 0; nt < 19; nt++) {
        int kc = nt * 8 + 2 * tg;
        int k = kc / CPROJ;
        int c = kc - k * CPROJ;
#pragma unroll
        for (int hh = 0; hh < 2; hh++) {
            int row = (hh == 0) ? row0 : row1;
            float v0 = cacc[nt][2 * hh + 0], v1 = cacc[nt][2 * hh + 1];
            int pos = sigma_k(k, l0 + row);
            if (c < RR) {
                float A0 = sAk[k * RR + c],     tb0 = sdtb[k * RR + c];
                float A1 = sAk[k * RR + c + 1], tb1 = sdtb[k * RR + c + 1];
                float x0 = v0 + tb0, x1 = v1 + tb1;
                float dt0 = (x0 > 20.f) ? x0 : log1pf(expf(x0));
                float dt1 = (x1 > 20.f) ? x1 : log1pf(expf(x1));
                float4 w = make_float4(dt0, expf(dt0 * A0), dt1, expf(dt1 * A1));
                *reinterpret_cast<float4*>(&d_dtdk[((b * LL + pos) * KK + k) * RR + c]) = w;
            } else {
                *reinterpret_cast<float2*>(&d_BC[((b * LL + pos) * KK + k) * 32 + (c - RR)]) =
                    make_float2(v0, v1);
            }
        }
    }
}

// ---------- K4A: staged u + f32x2 state pairs [round-11 exact] ----------
__global__ __launch_bounds__(192) void k4_scanA(const float* __restrict__ Ds) {
    __shared__ __align__(16) float4 sBC[TT * 8];   // 8KB
    __shared__ float2 sdt[TT * RR];                // 3KB
    __shared__ float  su[32 * DI];                 // 24KB
    int bx = blockIdx.x;                 // 2048 = b(8) * k(4) * chunk(64)
    int chunk = bx & 63, k = (bx >> 6) & 3, b = bx >> 8;
    int t = threadIdx.x;
    int warp = t >> 5, lane = t & 31;
    int l0 = chunk * TT;

    const float4* bc4 = reinterpret_cast<const float4*>(d_BC);
    int g4 = ((b * LL + l0) * KK + k) * 8;
    for (int j = t; j < TT * 8; j += 192) {
        int s = j >> 3, w = j & 7;
        sBC[j] = bc4[g4 + s * KK * 8 + w];
    }
    int gd = ((b * LL + l0) * KK + k) * RR;
    for (int j = t; j < TT * RR; j += 192) {
        int s = j / RR, r = j % RR;
        sdt[j] = d_dtdk[gd + s * KK * RR + r];
    }

    int ubase, ustride;
    if (k == 0)      { ubase = l0;        ustride = 1;   }
    else if (k == 1) { ubase = chunk;     ustride = 64;  }
    else if (k == 2) { ubase = 4095 - l0; ustride = -1;  }
    else             { ubase = 4095 - chunk; ustride = -64; }

    int r = warp;  // 0..5
    int sl = b * KRR + k * RR + r;
    float Dd = Ds[(k * RR + r) * 32 + lane];

    ull hp[8];
#pragma unroll
    for (int n = 0; n < 8; n++) hp[n] = 0ULL;
    float P = 1.f;
    int ysIdx = ((b * LL + l0) * KK + k) * 192 + r * 32 + lane;
    int pIdx  = sl * LL + l0;

    const float* ubp = d_xi + (long)(b * LL + ubase) * DI + t;
    long ustepL = (long)ustride * DI;
    const ulonglong2* sBC2 = reinterpret_cast<const ulonglong2*>(sBC);

#pragma unroll
    for (int half = 0; half < 2; half++) {
        __syncthreads();
        {
            const float* up = ubp + (long)(half * 32) * ustepL;
#pragma unroll 8
            for (int sl2 = 0; sl2 < 32; sl2++) {
                su[sl2 * DI + t] = *up;
                up += ustepL;
            }
        }
        __syncthreads();

#pragma unroll 2
        for (int s2 = 0; s2 < 32; s2++) {
            int s = half * 32 + s2;
            float u = su[s2 * DI + r * 32 + lane];
            float2 dd = sdt[s * RR + r];
            ulonglong2 b01 = sBC2[s * 8 + 0], b23 = sBC2[s * 8 + 1];
            ulonglong2 b45 = sBC2[s * 8 + 2], b67 = sBC2[s * 8 + 3];
            ulonglong2 c01 = sBC2[s * 8 + 4], c23 = sBC2[s * 8 + 5];
            ulonglong2 c45 = sBC2[s * 8 + 6], c67 = sBC2[s * 8 + 7];
            ull Bp[8] = {b01.x, b01.y, b23.x, b23.y, b45.x, b45.y, b67.x, b67.y};
            ull Cp[8] = {c01.x, c01.y, c23.x, c23.y, c45.x, c45.y, c67.x, c67.y};
            ull dkb = bcast2(dd.y);
            ull xub = bcast2(dd.x * u);
            ull yp = 0ULL;
#pragma unroll
            for (int n = 0; n < 8; n++) {
                hp[n] = fma2(dkb, hp[n], mul2(xub, Bp[n]));
                yp = fma2(hp[n], Cp[n], yp);
            }
            P *= dd.y;
            float2 yy = unpk(yp);
            d_ys[ysIdx] = fmaf(u, Dd, yy.x + yy.y);
            if (lane == 0) d_P[pIdx] = P;
            ysIdx += KK * 192; pIdx += 1;
        }
    }
    ulonglong2* hout = reinterpret_cast<ulonglong2*>(d_h + ((sl * NCH + chunk) * 32 + lane) * NN);
    hout[0] = make_ulonglong2(hp[0], hp[1]);
    hout[1] = make_ulonglong2(hp[2], hp[3]);
    hout[2] = make_ulonglong2(hp[4], hp[5]);
    hout[3] = make_ulonglong2(hp[6], hp[7]);
}

// ---------- K4B1: group-local carry (8 chunks per warp, parallel over 1536 warps) ----------
__global__ __launch_bounds__(256) void k4_b1() {
    int gw = (blockIdx.x * blockDim.x + threadIdx.x) >> 5;  // 0..1535
    int lane = threadIdx.x & 31;
    int sl = gw >> 3, g = gw & 7;

    float h[NN];
#pragma unroll
    for (int n = 0; n < NN; n++) h[n] = 0.f;
    float q = 1.f;

#pragma unroll
    for (int j = 0; j < GS; j++) {
        int c = g * GS + j;
        float4* dst = reinterpret_cast<float4*>(d_h0 + ((sl * NCH + c) * 32 + lane) * NN);
        dst[0] = make_float4(h[0], h[1], h[2], h[3]);
        dst[1] = make_float4(h[4], h[5], h[6], h[7]);
        dst[2] = make_float4(h[8], h[9], h[10], h[11]);
        dst[3] = make_float4(h[12], h[13], h[14], h[15]);
        if (lane == 0) d_Q[sl * NCH + c] = q;
        const float4* src = reinterpret_cast<const float4*>(d_h + ((sl * NCH + c) * 32 + lane) * NN);
        float4 a0 = src[0], a1 = src[1], a2 = src[2], a3 = src[3];
        float P = d_P[sl * LL + c * TT + TT - 1];
        float av[NN] = {a0.x,a0.y,a0.z,a0.w, a1.x,a1.y,a1.z,a1.w,
                        a2.x,a2.y,a2.z,a2.w, a3.x,a3.y,a3.z,a3.w};
#pragma unroll
        for (int n = 0; n < NN; n++) h[n] = fmaf(P, h[n], av[n]);
        q *= P;
    }
    float4* hg = reinterpret_cast<float4*>(d_hg + ((sl * NG + g) * 32 + lane) * NN);
    hg[0] = make_float4(h[0], h[1], h[2], h[3]);
    hg[1] = make_float4(h[4], h[5], h[6], h[7]);
    hg[2] = make_float4(h[8], h[9], h[10], h[11]);
    hg[3] = make_float4(h[12], h[13], h[14], h[15]);
    if (lane == 0) d_Dg[sl * NG + g] = q;
}

// ---------- K4B2: carry across 8 groups (192 warps, 8 serial steps) ----------
__global__ __launch_bounds__(256) void k4_b2() {
    int sl = (blockIdx.x * blockDim.x + threadIdx.x) >> 5;  // 0..191
    int lane = threadIdx.x & 31;
    float cr[NN];
#pragma unroll
    for (int n = 0; n < NN; n++) cr[n] = 0.f;
#pragma unroll
    for (int g = 0; g < NG; g++) {
        float4* dst = reinterpret_cast<float4*>(d_cr + ((sl * NG + g) * 32 + lane) * NN);
        dst[0] = make_float4(cr[0], cr[1], cr[2], cr[3]);
        dst[1] = make_float4(cr[4], cr[5], cr[6], cr[7]);
        dst[2] = make_float4(cr[8], cr[9], cr[10], cr[11]);
        dst[3] = make_float4(cr[12], cr[13], cr[14], cr[15]);
        const float4* hg = reinterpret_cast<const float4*>(d_hg + ((sl * NG + g) * 32 + lane) * NN);
        float4 a0 = hg[0], a1 = hg[1], a2 = hg[2], a3 = hg[3];
        float Dg = d_Dg[sl * NG + g];
        float av[NN] = {a0.x,a0.y,a0.z,a0.w, a1.x,a1.y,a1.z,a1.w,
                        a2.x,a2.y,a2.z,a2.w, a3.x,a3.y,a3.z,a3.w};
#pragma unroll
        for (int n = 0; n < NN; n++) cr[n] = fmaf(Dg, cr[n], av[n]);
    }
}

// ---------- K4C: fixup ys += P_l * ((h0_local + Q*carry) . C_l); f32x2 ----------
__global__ __launch_bounds__(192) void k4_scanC() {
    __shared__ __align__(16) float4 sC[TT * 4];  // 4KB
    __shared__ float sP[RR * TT];                // 1.5KB
    int bx = blockIdx.x;
    int chunk = bx & 63, k = (bx >> 6) & 3, b = bx >> 8;
    int t = threadIdx.x;
    int warp = t >> 5, lane = t & 31;
    int l0 = chunk * TT;
    int grp = chunk >> 3;

    const float4* bc4 = reinterpret_cast<const float4*>(d_BC);
    int g4 = ((b * LL + l0) * KK + k) * 8;
    for (int j = t; j < TT * 4; j += 192) {
        int s = j >> 2, w = j & 3;
        sC[j] = bc4[g4 + s * KK * 8 + 4 + w];
    }
    for (int j = t; j < RR * TT; j += 192) {
        int r = j / TT, s = j % TT;
        sP[j] = d_P[(b * KRR + k * RR + r) * LL + l0 + s];
    }
    __syncthreads();

    int r = warp;
    int sl = b * KRR + k * RR + r;
    // reconstruct h0 = h0_local + Q * carry (fused former k4_b3)
    float Q = d_Q[sl * NCH + chunk];
    const float4* hl = reinterpret_cast<const float4*>(
        d_h0 + ((sl * NCH + chunk) * 32 + lane) * NN);
    const float4* cr = reinterpret_cast<const float4*>(
        d_cr + ((sl * NG + grp) * 32 + lane) * NN);
    float h0f[NN];
#pragma unroll
    for (int qi = 0; qi < 4; qi++) {
        float4 hv = hl[qi], cv = cr[qi];
        h0f[4 * qi + 0] = fmaf(Q, cv.x, hv.x);
        h0f[4 * qi + 1] = fmaf(Q, cv.y, hv.y);
        h0f[4 * qi + 2] = fmaf(Q, cv.z, hv.z);
        h0f[4 * qi + 3] = fmaf(Q, cv.w, hv.w);
    }
    ull h0p[8];
#pragma unroll
    for (int n = 0; n < 8; n++) {
        ull lo, hi;
        asm("mov.b64 %0, {%1, %2};" : "=l"(lo) : "f"(h0f[2 * n]), "f"(h0f[2 * n + 1]));
        h0p[n] = lo; (void)hi;
    }

    const ulonglong2* sC2 = reinterpret_cast<const ulonglong2*>(sC);
    int ysIdx = ((b * LL + l0) * KK + k) * 192 + r * 32 + lane;
#pragma unroll 2
    for (int s = 0; s < TT; s++) {
        ulonglong2 c01 = sC2[s * 4 + 0], c23 = sC2[s * 4 + 1];
        ulonglong2 c45 = sC2[s * 4 + 2], c67 = sC2[s * 4 + 3];
        ull Cp[8] = {c01.x, c01.y, c23.x, c23.y, c45.x, c45.y, c67.x, c67.y};
        ull corrp = 0ULL;
#pragma unroll
        for (int n = 0; n < 8; n++) corrp = fma2(h0p[n], Cp[n], corrp);
        float2 cc = unpk(corrp);
        d_ys[ysIdx] = fmaf(sP[r * TT + s], cc.x + cc.y, d_ys[ysIdx]);
        ysIdx += KK * 192;
    }
}

// ---------- K5: cross-merge + LayerNorm + out-proj ----------
__global__ __launch_bounds__(192) void k5_out(const float* __restrict__ lng,
                                              const float* __restrict__ lnb,
                                              const float* __restrict__ wout,
                                              float* __restrict__ out) {
    __shared__ __align__(16) float sy[32 * DI];   // 24KB
    __shared__ float smu[32], srs[32];
    int t = threadIdx.x;  // 192
    int pb = blockIdx.x * 32;    // 32 | 4096: never crosses batch
    int b = pb >> 12;
    int lbase = pb & 4095;

    for (int p = 0; p < 32; p++) {
        int l = lbase + p;
        float v = 0.f;
#pragma unroll
        for (int k = 0; k < KK; k++) {
            int pos = sigma_k(k, l);
            v += d_ys[((b * LL + pos) * KK + k) * 192 + t];
        }
        sy[p * DI + t] = v;
    }
    __syncthreads();

    int warp = t >> 5, lane = t & 31;
    for (int p = warp; p < 32; p += 6) {
        float s1 = 0.f, s2 = 0.f;
#pragma unroll
        for (int j = 0; j < 6; j++) {
            float v = sy[p * DI + lane + j * 32];
            s1 += v; s2 = fmaf(v, v, s2);
        }
#pragma unroll
        for (int o = 16; o > 0; o >>= 1) {
            s1 += __shfl_down_sync(0xffffffffu, s1, o);
            s2 += __shfl_down_sync(0xffffffffu, s2, o);
        }
        if (lane == 0) {
            float mu = s1 * (1.f / DI);
            float var = s2 * (1.f / DI) - mu * mu;
            smu[p] = mu;
            srs[p] = rsqrtf(var + 1e-5f);
        }
    }
    __syncthreads();

    float g = lng[t], be = lnb[t];
    for (int p = 0; p < 32; p++)
        sy[p * DI + t] = (sy[p * DI + t] - smu[p]) * srs[p] * g + be;
    __syncthreads();

    const float4* sy4 = reinterpret_cast<const float4*>(sy);
    int row = t / 48;     // 0..3 -> pixels row*8 .. +7
    int col = t % 48;     // outputs 2col, 2col+1
    float a0[8], a1[8];
#pragma unroll
    for (int q = 0; q < 8; q++) { a0[q] = 0.f; a1[q] = 0.f; }
    for (int c4 = 0; c4 < DI / 4; c4++) {
        float2 w0 = *reinterpret_cast<const float2*>(&wout[(c4 * 4 + 0) * 96 + 2 * col]);
        float2 w1 = *reinterpret_cast<const float2*>(&wout[(c4 * 4 + 1) * 96 + 2 * col]);
        float2 w2 = *reinterpret_cast<const float2*>(&wout[(c4 * 4 + 2) * 96 + 2 * col]);
        float2 w3 = *reinterpret_cast<const float2*>(&wout[(c4 * 4 + 3) * 96 + 2 * col]);
#pragma unroll
        for (int q = 0; q < 8; q++) {
            float4 sv = sy4[(row * 8 + q) * (DI / 4) + c4];
            a0[q] = fmaf(sv.x, w0.x, a0[q]); a1[q] = fmaf(sv.x, w0.y, a1[q]);
            a0[q] = fmaf(sv.y, w1.x, a0[q]); a1[q] = fmaf(sv.y, w1.y, a1[q]);
            a0[q] = fmaf(sv.z, w2.x, a0[q]); a1[q] = fmaf(sv.z, w2.y, a1[q]);
            a0[q] = fmaf(sv.w, w3.x, a0[q]); a1[q] = fmaf(sv.w, w3.y, a1[q]);
        }
    }
#pragma unroll
    for (int q = 0; q < 8; q++) {
        float2 v = make_float2(a0[q], a1[q]);
        *reinterpret_cast<float2*>(&out[(pb + row * 8 + q) * 96 + 2 * col]) = v;
    }
}

extern "C" void kernel_launch(void* const* d_in, const int* in_sizes, int n_in,
                              void* d_out, int out_size) {
    const float* x    = (const float*)d_in[0];
    const float* w_in = (const float*)d_in[1];
    const float* wconv= (const float*)d_in[2];
    const float* bconv= (const float*)d_in[3];
    const float* xpw  = (const float*)d_in[4];
    const float* Alog = (const float*)d_in[5];
    const float* Ds   = (const float*)d_in[6];
    const float* dtb  = (const float*)d_in[7];
    const float* lng  = (const float*)d_in[8];
    const float* lnb  = (const float*)d_in[9];
    const float* wout = (const float*)d_in[10];
    float* out = (float*)d_out;

    cudaFuncSetAttribute(k3_mma, cudaFuncAttributeMaxDynamicSharedMemorySize, K3_SMEM_BYTES);

    k1_inproj<<<BB * LL / 32, 192>>>(x, w_in);
    k2_conv<<<BB * LL / 8, DI>>>(wconv, bconv);
    k3_mma<<<BB * LL / 128, 256, K3_SMEM_BYTES>>>(xpw, Alog, dtb);
    k4_scanA<<<BB * KK * NCH, 192>>>(Ds);
    k4_b1<<<192, 256>>>();
    k4_b2<<<24, 256>>>();
    k4_scanC<<<BB * KK * NCH, 192>>>();
    k5_out<<<BB * LL / 32, 192>>>(lng, lnb, wout, out);
}